// round 4
// baseline (speedup 1.0000x reference)
#include <cuda_runtime.h>
#include <cuda_bf16.h>
#include <math.h>
#include <stdint.h>

#define NLAYER 2
#define DMODEL 768
#define VOCAB  32000
#define DSTATE 16
#define DINNER 1536
#define DTRANK 48
#define BB 2
#define LL 1024
#define BL (BB*LL)
#define XDW 80   // DT_RANK + 2*D_STATE
#define CHK 128  // scan checkpoint interval
#define NCHK (LL/CHK)

// ---------------- scratch (device globals; no allocation allowed) ----------
__device__ float g_X   [BL*DMODEL];            // residual stream (fp32)
__device__ float g_XZ  [BL*2*DINNER];          // in_proj output
__device__ float g_U   [BL*DINNER];            // silu(conv(xs))
__device__ float g_XDBL[BL*XDW];               // x_proj output (delta|B|C)
__device__ float g_DT  [BL*DINNER];            // softplus(dt)
__device__ float g_SC  [BB*DINNER*DSTATE*NCHK];// scan suffix-sum checkpoints
// bf16 hi/lo split operands
__device__ __nv_bfloat16 g_XNh[BL*DMODEL],  g_XNl[BL*DMODEL];     // rmsnorm out
__device__ __nv_bfloat16 g_Yh [BL*DINNER],  g_Yl [BL*DINNER];     // scan out
__device__ __nv_bfloat16 g_Eh [VOCAB*DMODEL], g_El[VOCAB*DMODEL]; // embedding
__device__ __nv_bfloat16 g_Wih[2*DINNER*DMODEL], g_Wil[2*DINNER*DMODEL];
__device__ __nv_bfloat16 g_Woh[DMODEL*DINNER],   g_Wol[DMODEL*DINNER];

// ======================= PTX helpers (arch-neutral) =========================
__device__ __forceinline__ uint32_t smem_u32(const void* p) {
    uint32_t a;
    asm("{ .reg .u64 t; cvta.to.shared.u64 t, %1; cvt.u32.u64 %0, t; }"
        : "=r"(a) : "l"(p));
    return a;
}
__device__ __forceinline__ void cp16(uint32_t d, const void* s) {
    asm volatile("cp.async.cg.shared.global [%0], [%1], 16;" :: "r"(d), "l"(s));
}
#define CP_COMMIT() asm volatile("cp.async.commit_group;" ::: "memory")
#define CP_WAIT(N)  asm volatile("cp.async.wait_group %0;" :: "n"(N) : "memory")
#define LDSM4(r, a) \
    asm volatile("ldmatrix.sync.aligned.m8n8.x4.shared.b16 {%0,%1,%2,%3}, [%4];" \
        : "=r"((r)[0]), "=r"((r)[1]), "=r"((r)[2]), "=r"((r)[3]) : "r"(a))
#define MMA16816(d, a, b0, b1) \
    asm volatile("mma.sync.aligned.m16n8k16.row.col.f32.bf16.bf16.f32 " \
        "{%0,%1,%2,%3}, {%4,%5,%6,%7}, {%8,%9}, {%0,%1,%2,%3};" \
        : "+f"((d)[0]), "+f"((d)[1]), "+f"((d)[2]), "+f"((d)[3]) \
        : "r"((a)[0]), "r"((a)[1]), "r"((a)[2]), "r"((a)[3]), "r"(b0), "r"(b1))

// ============ split-bf16 mma.sync GEMM: C[M,N] = A[M,K]*B[N,K]^T ============
// A = Ah+Al, B = Bh+Bl (bf16 hi/lo). grid = (M/128, N/128). K % 32 == 0.
// M, N multiples of 128. mode 0: C = acc ; mode 1: C += acc.
// SMEM stage = 4 tiles x 128x32 bf16 (8KB each) = 32KB; 2 stages = 64KB.
// Tile layout: byte(row,chunk16) = row*64 + (((chunk)+(row>>1))&3)*16
// (8 consecutive rows at a fixed chunk hit 8 distinct 16B bank slots).
#define STAGE_B 32768
#define GSMEM   (2 * STAGE_B)
#define SWZOFF(row, chunk) ((uint32_t)((row) * 64 + ((((chunk) + ((row) >> 1)) & 3) << 4)))

__device__ __forceinline__ void load_tile(
    uint32_t dstb,
    const __nv_bfloat16* __restrict__ Ah, const __nv_bfloat16* __restrict__ Al,
    const __nv_bfloat16* __restrict__ Bh, const __nv_bfloat16* __restrict__ Bl,
    int brow, int bcol, int K, int kc, int tid)
{
    const int row0  = tid >> 2;
    const int chunk = tid & 3;
    const __nv_bfloat16* srcs[4] = {Ah, Al, Bh, Bl};
    const int r0s[4] = {brow, brow, bcol, bcol};
    #pragma unroll
    for (int m = 0; m < 4; m++) {
        #pragma unroll
        for (int i = 0; i < 2; i++) {
            int row = row0 + i * 64;
            const void* src = srcs[m] + (size_t)(r0s[m] + row) * K + kc * 32 + chunk * 8;
            cp16(dstb + m * 8192 + SWZOFF(row, chunk), src);
        }
    }
}

__global__ __launch_bounds__(256) void gemm_bf16s_kernel(
    const __nv_bfloat16* __restrict__ Ah, const __nv_bfloat16* __restrict__ Al,
    const __nv_bfloat16* __restrict__ Bh, const __nv_bfloat16* __restrict__ Bl,
    float* __restrict__ C, int ldc, int K, int mode)
{
    extern __shared__ char smem[];
    const uint32_t sbase = smem_u32(smem);
    const int tid  = threadIdx.x;
    const int warp = tid >> 5, lane = tid & 31;
    const int brow = blockIdx.x * 128;
    const int bcol = blockIdx.y * 128;
    const int wm = (warp >> 2) * 64;   // 0 / 64
    const int wn = (warp & 3) * 32;    // 0,32,64,96

    float acc[4][4][4];
    #pragma unroll
    for (int mi = 0; mi < 4; mi++)
        #pragma unroll
        for (int ni = 0; ni < 4; ni++)
            #pragma unroll
            for (int q = 0; q < 4; q++) acc[mi][ni][q] = 0.f;

    const int nk = K >> 5;

    load_tile(sbase, Ah, Al, Bh, Bl, brow, bcol, K, 0, tid);
    CP_COMMIT();

    // ldmatrix lane addressing (computed once)
    const int a_row = lane & 15;                       // + wm + mi*16
    const int a_kc  = lane >> 4;                       // 0/1 (k8 chunk)
    const int b_row = (lane & 7) + ((lane >> 4) << 3); // + wn + p*16
    const int b_kc  = (lane >> 3) & 1;

    for (int c = 0; c < nk; c++) {
        if (c + 1 < nk) {
            load_tile(sbase + ((c + 1) & 1) * STAGE_B, Ah, Al, Bh, Bl,
                      brow, bcol, K, c + 1, tid);
            CP_COMMIT();
            CP_WAIT(1);
        } else {
            CP_WAIT(0);
        }
        __syncthreads();

        const uint32_t tb = sbase + (c & 1) * STAGE_B;
        #pragma unroll
        for (int s = 0; s < 2; s++) {
            uint32_t ah[4][4], al[4][4], bh[2][4], bl[2][4];
            #pragma unroll
            for (int mi = 0; mi < 4; mi++) {
                int row = wm + mi * 16 + a_row;
                uint32_t a = tb + SWZOFF(row, 2 * s + a_kc);
                LDSM4(ah[mi], a);
                LDSM4(al[mi], a + 8192);
            }
            #pragma unroll
            for (int p = 0; p < 2; p++) {
                int row = wn + p * 16 + b_row;
                uint32_t a = tb + 16384 + SWZOFF(row, 2 * s + b_kc);
                LDSM4(bh[p], a);
                LDSM4(bl[p], a + 8192);
            }
            #pragma unroll
            for (int mi = 0; mi < 4; mi++)
                #pragma unroll
                for (int ni = 0; ni < 4; ni++) {
                    const int p = ni >> 1, sb = (ni & 1) * 2;
                    MMA16816(acc[mi][ni], ah[mi], bh[p][sb], bh[p][sb + 1]);
                    MMA16816(acc[mi][ni], ah[mi], bl[p][sb], bl[p][sb + 1]);
                    MMA16816(acc[mi][ni], al[mi], bh[p][sb], bh[p][sb + 1]);
                }
        }
        __syncthreads();
    }

    // epilogue: d0,d1 -> (g, 2t),(g, 2t+1) ; d2,d3 -> (g+8, ...)
    const int g = lane >> 2, t = lane & 3;
    #pragma unroll
    for (int mi = 0; mi < 4; mi++) {
        int row0 = brow + wm + mi * 16 + g;
        #pragma unroll
        for (int ni = 0; ni < 4; ni++) {
            int col = bcol + wn + ni * 8 + 2 * t;
            float2* p0 = (float2*)(C + (size_t)row0 * ldc + col);
            float2* p1 = (float2*)(C + (size_t)(row0 + 8) * ldc + col);
            if (mode == 1) {
                float2 o0 = *p0, o1 = *p1;
                o0.x += acc[mi][ni][0]; o0.y += acc[mi][ni][1];
                o1.x += acc[mi][ni][2]; o1.y += acc[mi][ni][3];
                *p0 = o0; *p1 = o1;
            } else {
                *p0 = make_float2(acc[mi][ni][0], acc[mi][ni][1]);
                *p1 = make_float2(acc[mi][ni][2], acc[mi][ni][3]);
            }
        }
    }
}

// ---------------- fp32 -> bf16 hi/lo split (weights) ------------------------
__global__ void split_kernel(const float* __restrict__ S,
                             __nv_bfloat16* __restrict__ H,
                             __nv_bfloat16* __restrict__ L, int n4) {
    int i = blockIdx.x * blockDim.x + threadIdx.x;
    if (i >= n4) return;
    float4 v = ((const float4*)S)[i];
    __nv_bfloat16 h0 = __float2bfloat16(v.x), h1 = __float2bfloat16(v.y);
    __nv_bfloat16 h2 = __float2bfloat16(v.z), h3 = __float2bfloat16(v.w);
    __nv_bfloat16 l0 = __float2bfloat16(v.x - __bfloat162float(h0));
    __nv_bfloat16 l1 = __float2bfloat16(v.y - __bfloat162float(h1));
    __nv_bfloat16 l2 = __float2bfloat16(v.z - __bfloat162float(h2));
    __nv_bfloat16 l3 = __float2bfloat16(v.w - __bfloat162float(h3));
    __nv_bfloat162 a; a.x = h0; a.y = h1;
    __nv_bfloat162 b; b.x = h2; b.y = h3;
    ((__nv_bfloat162*)H)[i * 2] = a; ((__nv_bfloat162*)H)[i * 2 + 1] = b;
    a.x = l0; a.y = l1; b.x = l2; b.y = l3;
    ((__nv_bfloat162*)L)[i * 2] = a; ((__nv_bfloat162*)L)[i * 2 + 1] = b;
}

// ---------------- embedding gather -----------------------------------------
__global__ void embed_kernel(const int* __restrict__ ids,
                             const float* __restrict__ emb,
                             float* __restrict__ X) {
    int r = blockIdx.x;
    int id = ids[r];
    const float* src = emb + (size_t)id * DMODEL;
    float* dst = X + (size_t)r * DMODEL;
    for (int d = threadIdx.x; d < DMODEL; d += blockDim.x) dst[d] = src[d];
}

// ---------------- rmsnorm (fused bf16 hi/lo split output) -------------------
__global__ void rmsnorm_kernel(const float* __restrict__ X,
                               const float* __restrict__ w,
                               __nv_bfloat16* __restrict__ OH,
                               __nv_bfloat16* __restrict__ OL) {
    int r = blockIdx.x;
    const float* x = X + (size_t)r * DMODEL;
    float s = 0.f;
    for (int d = threadIdx.x; d < DMODEL; d += 256) { float v = x[d]; s += v * v; }
    __shared__ float sh[8];
    int lane = threadIdx.x & 31, wrp = threadIdx.x >> 5;
    #pragma unroll
    for (int o = 16; o > 0; o >>= 1) s += __shfl_xor_sync(0xffffffffu, s, o);
    if (lane == 0) sh[wrp] = s;
    __syncthreads();
    if (threadIdx.x == 0) {
        float t = 0.f;
        #pragma unroll
        for (int i = 0; i < 8; i++) t += sh[i];
        sh[0] = rsqrtf(t / (float)DMODEL + 1e-5f);
    }
    __syncthreads();
    float inv = sh[0];
    for (int d = threadIdx.x; d < DMODEL; d += 256) {
        float v = x[d] * inv * w[d];
        __nv_bfloat16 h = __float2bfloat16(v);
        OH[(size_t)r * DMODEL + d] = h;
        OL[(size_t)r * DMODEL + d] = __float2bfloat16(v - __bfloat162float(h));
    }
}

// ---------------- 3xTF32 split mma.sync GEMM (small shapes) -----------------
// mode 0: C = acc ; mode 2: C = softplus(acc + bias[col])
__device__ __forceinline__ uint32_t f2tf(float f) {
    uint32_t r;
    asm("cvt.rna.tf32.f32 %0, %1;" : "=r"(r) : "f"(f));
    return r;
}
#define KSTR 20

__global__ __launch_bounds__(256) void gemm_tf32s_kernel(
    const float* __restrict__ A, int lda,
    const float* __restrict__ B, int ldb,
    float* __restrict__ C, int ldc,
    int M, int N, int K, int mode, const float* __restrict__ bias)
{
    __shared__ uint32_t Ash[128 * KSTR], Asl[128 * KSTR];
    __shared__ uint32_t Bsh[128 * KSTR], Bsl[128 * KSTR];

    const int tid  = threadIdx.x;
    const int warp = tid >> 5;
    const int lane = tid & 31;
    const int g = lane >> 2, t = lane & 3;
    const int wm = (warp >> 2) * 64;
    const int wn = (warp & 3) * 32;
    const int brow = blockIdx.y * 128;
    const int bcol = blockIdx.x * 128;
    const int gr0 = tid >> 2;
    const int gr1 = (tid + 256) >> 2;
    const int gk  = (tid & 3) * 4;

    float c[4][4][4];
    #pragma unroll
    for (int mi = 0; mi < 4; mi++)
        #pragma unroll
        for (int ni = 0; ni < 4; ni++)
            #pragma unroll
            for (int q = 0; q < 4; q++) c[mi][ni][q] = 0.f;

    const int nk = K / 16;
    float4 aR0, aR1, bR0, bR1;
    const bool bv0 = (bcol + gr0) < N;
    const bool bv1 = (bcol + gr1) < N;

    aR0 = *(const float4*)&A[(size_t)(brow + gr0) * lda + gk];
    aR1 = *(const float4*)&A[(size_t)(brow + gr1) * lda + gk];
    bR0 = bv0 ? *(const float4*)&B[(size_t)(bcol + gr0) * ldb + gk] : make_float4(0,0,0,0);
    bR1 = bv1 ? *(const float4*)&B[(size_t)(bcol + gr1) * ldb + gk] : make_float4(0,0,0,0);

    for (int kt = 0; kt < nk; kt++) {
        __syncthreads();
        #pragma unroll
        for (int q = 0; q < 4; q++) {
            float av0 = (&aR0.x)[q], av1 = (&aR1.x)[q];
            float bw0 = (&bR0.x)[q], bw1 = (&bR1.x)[q];
            uint32_t h;
            h = f2tf(av0); Ash[gr0*KSTR+gk+q] = h; Asl[gr0*KSTR+gk+q] = f2tf(av0 - __uint_as_float(h));
            h = f2tf(av1); Ash[gr1*KSTR+gk+q] = h; Asl[gr1*KSTR+gk+q] = f2tf(av1 - __uint_as_float(h));
            h = f2tf(bw0); Bsh[gr0*KSTR+gk+q] = h; Bsl[gr0*KSTR+gk+q] = f2tf(bw0 - __uint_as_float(h));
            h = f2tf(bw1); Bsh[gr1*KSTR+gk+q] = h; Bsl[gr1*KSTR+gk+q] = f2tf(bw1 - __uint_as_float(h));
        }
        __syncthreads();

        if (kt + 1 < nk) {
            int k0 = (kt + 1) * 16;
            aR0 = *(const float4*)&A[(size_t)(brow + gr0) * lda + k0 + gk];
            aR1 = *(const float4*)&A[(size_t)(brow + gr1) * lda + k0 + gk];
            bR0 = bv0 ? *(const float4*)&B[(size_t)(bcol + gr0) * ldb + k0 + gk] : make_float4(0,0,0,0);
            bR1 = bv1 ? *(const float4*)&B[(size_t)(bcol + gr1) * ldb + k0 + gk] : make_float4(0,0,0,0);
        }

        #pragma unroll
        for (int ks = 0; ks < 16; ks += 8) {
            uint32_t afh[4][4], afl[4][4], bfh[4][2], bfl[4][2];
            #pragma unroll
            for (int mi = 0; mi < 4; mi++) {
                int mr = wm + mi * 16;
                afh[mi][0] = Ash[(mr+g  )*KSTR+ks+t  ]; afl[mi][0] = Asl[(mr+g  )*KSTR+ks+t  ];
                afh[mi][1] = Ash[(mr+g+8)*KSTR+ks+t  ]; afl[mi][1] = Asl[(mr+g+8)*KSTR+ks+t  ];
                afh[mi][2] = Ash[(mr+g  )*KSTR+ks+t+4]; afl[mi][2] = Asl[(mr+g  )*KSTR+ks+t+4];
                afh[mi][3] = Ash[(mr+g+8)*KSTR+ks+t+4]; afl[mi][3] = Asl[(mr+g+8)*KSTR+ks+t+4];
            }
            #pragma unroll
            for (int ni = 0; ni < 4; ni++) {
                int nr = wn + ni * 8;
                bfh[ni][0] = Bsh[(nr+g)*KSTR+ks+t  ]; bfl[ni][0] = Bsl[(nr+g)*KSTR+ks+t  ];
                bfh[ni][1] = Bsh[(nr+g)*KSTR+ks+t+4]; bfl[ni][1] = Bsl[(nr+g)*KSTR+ks+t+4];
            }
            #pragma unroll
            for (int mi = 0; mi < 4; mi++)
                #pragma unroll
                for (int ni = 0; ni < 4; ni++) {
                    #define MMA_TF32(AF, BF) \
                        asm volatile("mma.sync.aligned.m16n8k8.row.col.f32.tf32.tf32.f32 " \
                            "{%0,%1,%2,%3}, {%4,%5,%6,%7}, {%8,%9}, {%0,%1,%2,%3};\n" \
                            : "+f"(c[mi][ni][0]), "+f"(c[mi][ni][1]), \
                              "+f"(c[mi][ni][2]), "+f"(c[mi][ni][3]) \
                            : "r"(AF[mi][0]), "r"(AF[mi][1]), "r"(AF[mi][2]), "r"(AF[mi][3]), \
                              "r"(BF[ni][0]), "r"(BF[ni][1]))
                    MMA_TF32(afh, bfh);
                    MMA_TF32(afh, bfl);
                    MMA_TF32(afl, bfh);
                    #undef MMA_TF32
                }
        }
    }

    #pragma unroll
    for (int mi = 0; mi < 4; mi++) {
        int r0 = brow + wm + mi * 16 + g;
        #pragma unroll
        for (int ni = 0; ni < 4; ni++) {
            int col = bcol + wn + ni * 8 + 2 * t;
            #pragma unroll
            for (int q = 0; q < 4; q++) {
                int rr = r0 + (q >> 1) * 8;
                int cc = col + (q & 1);
                if (cc < N) {
                    size_t idx = (size_t)rr * ldc + cc;
                    float v = c[mi][ni][q];
                    if (mode == 2) {
                        v += bias[cc];
                        v = fmaxf(v, 0.f) + log1pf(expf(-fabsf(v)));
                    }
                    C[idx] = v;
                }
            }
        }
    }
}

// ---------------- depthwise causal conv (k=4) + silu ------------------------
__global__ void conv_silu_kernel(const float* __restrict__ XZ,
                                 const float* __restrict__ cw,
                                 const float* __restrict__ cb,
                                 float* __restrict__ U) {
    int d = blockIdx.x * blockDim.x + threadIdx.x;
    int r = blockIdx.y;
    if (d >= DINNER) return;
    int l = r & (LL - 1);
    float w0 = cw[d*4+0], w1 = cw[d*4+1], w2 = cw[d*4+2], w3 = cw[d*4+3];
    const float* Xp = XZ + (size_t)r * (2 * DINNER) + d;
    float acc = cb[d] + w3 * Xp[0];
    if (l >= 1) acc += w2 * Xp[-(2 * DINNER)];
    if (l >= 2) acc += w1 * Xp[-2 * (2 * DINNER)];
    if (l >= 3) acc += w0 * Xp[-3 * (2 * DINNER)];
    U[(size_t)r * DINNER + d] = acc / (1.f + expf(-acc));
}

// ---------------- selective scan (exp-of-suffix-cumsum formulation) ---------
__global__ void scan_kernel(const float* __restrict__ DT, const float* __restrict__ U,
                            const float* __restrict__ XD, const float* __restrict__ Alog,
                            const float* __restrict__ Dp, const float* __restrict__ XZ,
                            __nv_bfloat16* __restrict__ YH, __nv_bfloat16* __restrict__ YL,
                            float* __restrict__ SC)
{
    int b  = blockIdx.y;
    int n  = threadIdx.x & 15;
    int dl = threadIdx.x >> 4;
    int d  = blockIdx.x * 16 + dl;
    float A = -expf(Alog[d * DSTATE + n]);
    size_t cbase = ((size_t)b * DINNER * DSTATE + (size_t)d * DSTATE + n) * NCHK;

    float S = 0.f;
    for (int l = LL - 1; l >= 0; --l) {
        int r = b * LL + l;
        if ((l & (CHK - 1)) == 0) SC[cbase + (l >> 7)] = S;
        S += DT[(size_t)r * DINNER + d] * A;
    }

    float num = 0.f;
    float Dv = Dp[d];
    S = 0.f;
    for (int l = 0; l < LL; ++l) {
        int r = b * LL + l;
        float dt = DT[(size_t)r * DINNER + d];
        if ((l & (CHK - 1)) == 0) S = SC[cbase + (l >> 7)];
        else S -= dt * A;
        float es = expf(S);
        float u  = U[(size_t)r * DINNER + d];
        float Bm = XD[(size_t)r * XDW + DTRANK + n];
        float Cm = XD[(size_t)r * XDW + DTRANK + DSTATE + n];
        num += dt * u * Bm * es;
        float part = (num / (es + 1e-12f)) * Cm;
        part += __shfl_xor_sync(0xffffffffu, part, 8);
        part += __shfl_xor_sync(0xffffffffu, part, 4);
        part += __shfl_xor_sync(0xffffffffu, part, 2);
        part += __shfl_xor_sync(0xffffffffu, part, 1);
        if (n == 0) {
            float y   = part + u * Dv;
            float res = XZ[(size_t)r * (2 * DINNER) + DINNER + d];
            float yv  = y * (res / (1.f + expf(-res)));
            __nv_bfloat16 h = __float2bfloat16(yv);
            YH[(size_t)r * DINNER + d] = h;
            YL[(size_t)r * DINNER + d] = __float2bfloat16(yv - __bfloat162float(h));
        }
    }
}

// ---------------- driver ----------------------------------------------------
extern "C" void kernel_launch(void* const* d_in, const int* in_sizes, int n_in,
                              void* d_out, int out_size) {
    const int*   ids       = (const int*)  d_in[0];
    const float* emb       = (const float*)d_in[1];
    const float* W_in      = (const float*)d_in[2];
    const float* conv_w    = (const float*)d_in[3];
    const float* conv_b    = (const float*)d_in[4];
    const float* x_proj_w  = (const float*)d_in[5];
    const float* dt_proj_w = (const float*)d_in[6];
    const float* dt_proj_b = (const float*)d_in[7];
    const float* A_log     = (const float*)d_in[8];
    const float* D_param   = (const float*)d_in[9];
    const float* W_out     = (const float*)d_in[10];
    const float* norm_w    = (const float*)d_in[11];
    const float* norm_f_w  = (const float*)d_in[12];
    float* out = (float*)d_out;

    float *pX, *pXZ, *pU, *pXDBL, *pDT, *pSC;
    __nv_bfloat16 *pXNh, *pXNl, *pYh, *pYl, *pEh, *pEl, *pWih, *pWil, *pWoh, *pWol;
    cudaGetSymbolAddress((void**)&pX,    g_X);
    cudaGetSymbolAddress((void**)&pXZ,   g_XZ);
    cudaGetSymbolAddress((void**)&pU,    g_U);
    cudaGetSymbolAddress((void**)&pXDBL, g_XDBL);
    cudaGetSymbolAddress((void**)&pDT,   g_DT);
    cudaGetSymbolAddress((void**)&pSC,   g_SC);
    cudaGetSymbolAddress((void**)&pXNh,  g_XNh);
    cudaGetSymbolAddress((void**)&pXNl,  g_XNl);
    cudaGetSymbolAddress((void**)&pYh,   g_Yh);
    cudaGetSymbolAddress((void**)&pYl,   g_Yl);
    cudaGetSymbolAddress((void**)&pEh,   g_Eh);
    cudaGetSymbolAddress((void**)&pEl,   g_El);
    cudaGetSymbolAddress((void**)&pWih,  g_Wih);
    cudaGetSymbolAddress((void**)&pWil,  g_Wil);
    cudaGetSymbolAddress((void**)&pWoh,  g_Woh);
    cudaGetSymbolAddress((void**)&pWol,  g_Wol);

    static int smem_set = 0;
    if (!smem_set) {
        cudaFuncSetAttribute(gemm_bf16s_kernel,
                             cudaFuncAttributeMaxDynamicSharedMemorySize, GSMEM);
        smem_set = 1;
    }

    embed_kernel<<<BL, 256>>>(ids, emb, pX);
    // split embedding matrix (for logits GEMM B operand)
    split_kernel<<<(VOCAB * DMODEL / 4 + 255) / 256, 256>>>(emb, pEh, pEl, VOCAB * DMODEL / 4);

    for (int i = 0; i < NLAYER; i++) {
        rmsnorm_kernel<<<BL, 256>>>(pX, norm_w + (size_t)i * DMODEL, pXNh, pXNl);

        split_kernel<<<(2 * DINNER * DMODEL / 4 + 255) / 256, 256>>>(
            W_in + (size_t)i * 2 * DINNER * DMODEL, pWih, pWil, 2 * DINNER * DMODEL / 4);

        // xz = xn @ W_in^T : (2048,3072) K=768
        gemm_bf16s_kernel<<<dim3(BL / 128, 2 * DINNER / 128), 256, GSMEM>>>(
            pXNh, pXNl, pWih, pWil, pXZ, 2 * DINNER, DMODEL, 0);

        conv_silu_kernel<<<dim3(DINNER / 256, BL), 256>>>(
            pXZ, conv_w + (size_t)i * DINNER * 4, conv_b + (size_t)i * DINNER, pU);

        // x_dbl = u @ x_proj_w^T : (2048,80) K=1536 — 3xTF32 split
        gemm_tf32s_kernel<<<dim3(1, BL / 128), 256>>>(
            pU, DINNER, x_proj_w + (size_t)i * XDW * DINNER, DINNER,
            pXDBL, XDW, BL, XDW, DINNER, 0, nullptr);

        // dt = softplus(x_dbl[:, :48] @ dt_proj_w^T + b) : (2048,1536) K=48
        gemm_tf32s_kernel<<<dim3(DINNER / 128, BL / 128), 256>>>(
            pXDBL, XDW, dt_proj_w + (size_t)i * DINNER * DTRANK, DTRANK,
            pDT, DINNER, BL, DINNER, DTRANK, 2, dt_proj_b + (size_t)i * DINNER);

        scan_kernel<<<dim3(DINNER / 16, BB), 256>>>(
            pDT, pU, pXDBL, A_log + (size_t)i * DINNER * DSTATE,
            D_param + (size_t)i * DINNER, pXZ, pYh, pYl, pSC);

        split_kernel<<<(DMODEL * DINNER / 4 + 255) / 256, 256>>>(
            W_out + (size_t)i * DMODEL * DINNER, pWoh, pWol, DMODEL * DINNER / 4);

        // x += y @ W_out^T : (2048,768) K=1536, accumulate residual
        gemm_bf16s_kernel<<<dim3(BL / 128, DMODEL / 128), 256, GSMEM>>>(
            pYh, pYl, pWoh, pWol, pX, DMODEL, DINNER, 1);
    }

    rmsnorm_kernel<<<BL, 256>>>(pX, norm_f_w, pXNh, pXNl);

    // logits = xn @ emb^T : (2048,32000) K=768
    gemm_bf16s_kernel<<<dim3(BL / 128, VOCAB / 128), 256, GSMEM>>>(
        pXNh, pXNl, pEh, pEl, out, VOCAB, DMODEL, 0);
}

// round 5
// speedup vs baseline: 1.0355x; 1.0355x over previous
#include <cuda_runtime.h>
#include <cuda_bf16.h>
#include <math.h>
#include <stdint.h>

#define NLAYER 2
#define DMODEL 768
#define VOCAB  32000
#define DSTATE 16
#define DINNER 1536
#define DTRANK 48
#define BB 2
#define LL 1024
#define BL (BB*LL)
#define XDW 80   // DT_RANK + 2*D_STATE
#define CHK 128  // scan checkpoint interval
#define NCHK (LL/CHK)

// ---------------- scratch (device globals; no allocation allowed) ----------
__device__ float g_X   [BL*DMODEL];            // residual stream (fp32)
__device__ float g_XZ  [BL*2*DINNER];          // in_proj output
__device__ float g_U   [BL*DINNER];            // silu(conv(xs))
__device__ float g_XDBL[BL*XDW];               // x_proj output (delta|B|C)
__device__ float g_DT  [BL*DINNER];            // softplus(dt)
__device__ float g_SC  [BB*DINNER*DSTATE*NCHK];// scan suffix-sum checkpoints
// bf16 hi/lo split operands
__device__ __nv_bfloat16 g_XNh[BL*DMODEL],  g_XNl[BL*DMODEL];     // rmsnorm out
__device__ __nv_bfloat16 g_Yh [BL*DINNER],  g_Yl [BL*DINNER];     // scan out
__device__ __nv_bfloat16 g_Eh [VOCAB*DMODEL], g_El[VOCAB*DMODEL]; // embedding
__device__ __nv_bfloat16 g_Wih[2*DINNER*DMODEL], g_Wil[2*DINNER*DMODEL];
__device__ __nv_bfloat16 g_Woh[DMODEL*DINNER],   g_Wol[DMODEL*DINNER];

// ======================= PTX helpers (arch-neutral) =========================
__device__ __forceinline__ uint32_t smem_u32(const void* p) {
    uint32_t a;
    asm("{ .reg .u64 t; cvta.to.shared.u64 t, %1; cvt.u32.u64 %0, t; }"
        : "=r"(a) : "l"(p));
    return a;
}
__device__ __forceinline__ void cp16(uint32_t d, const void* s) {
    asm volatile("cp.async.cg.shared.global [%0], [%1], 16;" :: "r"(d), "l"(s));
}
#define CP_COMMIT() asm volatile("cp.async.commit_group;" ::: "memory")
#define CP_WAIT(N)  asm volatile("cp.async.wait_group %0;" :: "n"(N) : "memory")
#define LDSM4(r, a) \
    asm volatile("ldmatrix.sync.aligned.m8n8.x4.shared.b16 {%0,%1,%2,%3}, [%4];" \
        : "=r"((r)[0]), "=r"((r)[1]), "=r"((r)[2]), "=r"((r)[3]) : "r"(a))
#define MMA16816(d, a, b0, b1) \
    asm volatile("mma.sync.aligned.m16n8k16.row.col.f32.bf16.bf16.f32 " \
        "{%0,%1,%2,%3}, {%4,%5,%6,%7}, {%8,%9}, {%0,%1,%2,%3};" \
        : "+f"((d)[0]), "+f"((d)[1]), "+f"((d)[2]), "+f"((d)[3]) \
        : "r"((a)[0]), "r"((a)[1]), "r"((a)[2]), "r"((a)[3]), "r"(b0), "r"(b1))

// ============ split-bf16 mma.sync GEMM: C[M,N] = A[M,K]*B[N,K]^T ============
// A = Ah+Al, B = Bh+Bl (bf16 hi/lo). grid = (M/128, N/128). K % 32 == 0.
// mode 0: C = acc ; mode 1: C += acc.
// 3-stage cp.async pipeline; stage = 4 tiles x 128x32 bf16 = 32KB.
// Tile layout: byte(row,chunk16) = row*64 + (((chunk)+(row>>1))&3)*16
#define STAGE_B 32768
#define NSTAGE  3
#define GSMEM   (NSTAGE * STAGE_B)
#define SWZOFF(row, chunk) ((uint32_t)((row) * 64 + ((((chunk) + ((row) >> 1)) & 3) << 4)))

__device__ __forceinline__ void load_tile(
    uint32_t dstb,
    const __nv_bfloat16* __restrict__ Ah, const __nv_bfloat16* __restrict__ Al,
    const __nv_bfloat16* __restrict__ Bh, const __nv_bfloat16* __restrict__ Bl,
    int brow, int bcol, int K, int kc, int tid)
{
    const int row0  = tid >> 2;
    const int chunk = tid & 3;
    const __nv_bfloat16* srcs[4] = {Ah, Al, Bh, Bl};
    const int r0s[4] = {brow, brow, bcol, bcol};
    #pragma unroll
    for (int m = 0; m < 4; m++) {
        #pragma unroll
        for (int i = 0; i < 2; i++) {
            int row = row0 + i * 64;
            const void* src = srcs[m] + (size_t)(r0s[m] + row) * K + kc * 32 + chunk * 8;
            cp16(dstb + m * 8192 + SWZOFF(row, chunk), src);
        }
    }
}

__global__ __launch_bounds__(256, 2) void gemm_bf16s_kernel(
    const __nv_bfloat16* __restrict__ Ah, const __nv_bfloat16* __restrict__ Al,
    const __nv_bfloat16* __restrict__ Bh, const __nv_bfloat16* __restrict__ Bl,
    float* __restrict__ C, int ldc, int K, int mode)
{
    extern __shared__ char smem[];
    const uint32_t sbase = smem_u32(smem);
    const int tid  = threadIdx.x;
    const int warp = tid >> 5, lane = tid & 31;
    const int brow = blockIdx.x * 128;
    const int bcol = blockIdx.y * 128;
    const int wm = (warp >> 2) * 64;   // 0 / 64
    const int wn = (warp & 3) * 32;    // 0,32,64,96

    float acc[4][4][4];
    #pragma unroll
    for (int mi = 0; mi < 4; mi++)
        #pragma unroll
        for (int ni = 0; ni < 4; ni++)
            #pragma unroll
            for (int q = 0; q < 4; q++) acc[mi][ni][q] = 0.f;

    const int nk = K >> 5;

    // prologue: stages 0,1
    load_tile(sbase, Ah, Al, Bh, Bl, brow, bcol, K, 0, tid);
    CP_COMMIT();
    if (nk > 1)
        load_tile(sbase + STAGE_B, Ah, Al, Bh, Bl, brow, bcol, K, 1, tid);
    CP_COMMIT();

    // ldmatrix lane addressing
    const int a_row = lane & 15;
    const int a_kc  = lane >> 4;
    const int b_row = (lane & 7) + ((lane >> 4) << 3);
    const int b_kc  = (lane >> 3) & 1;

    int stg = 0;           // c % 3
    int stg2 = 2;          // (c+2) % 3
    for (int c = 0; c < nk; c++) {
        CP_WAIT(1);
        __syncthreads();

        const uint32_t tb = sbase + stg * STAGE_B;
        #pragma unroll
        for (int s = 0; s < 2; s++) {
            uint32_t bh[2][4], bl[2][4];
            #pragma unroll
            for (int p = 0; p < 2; p++) {
                int row = wn + p * 16 + b_row;
                uint32_t a = tb + 16384 + SWZOFF(row, 2 * s + b_kc);
                LDSM4(bh[p], a);
                LDSM4(bl[p], a + 8192);
            }
            #pragma unroll
            for (int mi = 0; mi < 4; mi++) {
                uint32_t ah[4], al[4];
                int row = wm + mi * 16 + a_row;
                uint32_t a = tb + SWZOFF(row, 2 * s + a_kc);
                LDSM4(ah, a);
                LDSM4(al, a + 8192);
                #pragma unroll
                for (int ni = 0; ni < 4; ni++) {
                    const int p = ni >> 1, sb = (ni & 1) * 2;
                    MMA16816(acc[mi][ni], ah, bh[p][sb], bh[p][sb + 1]);
                    MMA16816(acc[mi][ni], ah, bl[p][sb], bl[p][sb + 1]);
                    MMA16816(acc[mi][ni], al, bh[p][sb], bh[p][sb + 1]);
                }
            }
        }

        if (c + 2 < nk)
            load_tile(sbase + stg2 * STAGE_B, Ah, Al, Bh, Bl, brow, bcol, K, c + 2, tid);
        CP_COMMIT();

        stg  = (stg  == 2) ? 0 : stg  + 1;
        stg2 = (stg2 == 2) ? 0 : stg2 + 1;
    }

    // epilogue
    const int g = lane >> 2, t = lane & 3;
    #pragma unroll
    for (int mi = 0; mi < 4; mi++) {
        int row0 = brow + wm + mi * 16 + g;
        #pragma unroll
        for (int ni = 0; ni < 4; ni++) {
            int col = bcol + wn + ni * 8 + 2 * t;
            float2* p0 = (float2*)(C + (size_t)row0 * ldc + col);
            float2* p1 = (float2*)(C + (size_t)(row0 + 8) * ldc + col);
            if (mode == 1) {
                float2 o0 = *p0, o1 = *p1;
                o0.x += acc[mi][ni][0]; o0.y += acc[mi][ni][1];
                o1.x += acc[mi][ni][2]; o1.y += acc[mi][ni][3];
                *p0 = o0; *p1 = o1;
            } else {
                *p0 = make_float2(acc[mi][ni][0], acc[mi][ni][1]);
                *p1 = make_float2(acc[mi][ni][2], acc[mi][ni][3]);
            }
        }
    }
}

// ---------------- fp32 -> bf16 hi/lo split (weights) ------------------------
__global__ void split_kernel(const float* __restrict__ S,
                             __nv_bfloat16* __restrict__ H,
                             __nv_bfloat16* __restrict__ L, int n4) {
    int i = blockIdx.x * blockDim.x + threadIdx.x;
    if (i >= n4) return;
    float4 v = ((const float4*)S)[i];
    __nv_bfloat16 h0 = __float2bfloat16(v.x), h1 = __float2bfloat16(v.y);
    __nv_bfloat16 h2 = __float2bfloat16(v.z), h3 = __float2bfloat16(v.w);
    __nv_bfloat16 l0 = __float2bfloat16(v.x - __bfloat162float(h0));
    __nv_bfloat16 l1 = __float2bfloat16(v.y - __bfloat162float(h1));
    __nv_bfloat16 l2 = __float2bfloat16(v.z - __bfloat162float(h2));
    __nv_bfloat16 l3 = __float2bfloat16(v.w - __bfloat162float(h3));
    __nv_bfloat162 a; a.x = h0; a.y = h1;
    __nv_bfloat162 b; b.x = h2; b.y = h3;
    ((__nv_bfloat162*)H)[i * 2] = a; ((__nv_bfloat162*)H)[i * 2 + 1] = b;
    a.x = l0; a.y = l1; b.x = l2; b.y = l3;
    ((__nv_bfloat162*)L)[i * 2] = a; ((__nv_bfloat162*)L)[i * 2 + 1] = b;
}

// ---------------- embedding gather -----------------------------------------
__global__ void embed_kernel(const int* __restrict__ ids,
                             const float* __restrict__ emb,
                             float* __restrict__ X) {
    int r = blockIdx.x;
    int id = ids[r];
    const float* src = emb + (size_t)id * DMODEL;
    float* dst = X + (size_t)r * DMODEL;
    for (int d = threadIdx.x; d < DMODEL; d += blockDim.x) dst[d] = src[d];
}

// ---------------- rmsnorm (fused bf16 hi/lo split output) -------------------
__global__ void rmsnorm_kernel(const float* __restrict__ X,
                               const float* __restrict__ w,
                               __nv_bfloat16* __restrict__ OH,
                               __nv_bfloat16* __restrict__ OL) {
    int r = blockIdx.x;
    const float* x = X + (size_t)r * DMODEL;
    float s = 0.f;
    for (int d = threadIdx.x; d < DMODEL; d += 256) { float v = x[d]; s += v * v; }
    __shared__ float sh[8];
    int lane = threadIdx.x & 31, wrp = threadIdx.x >> 5;
    #pragma unroll
    for (int o = 16; o > 0; o >>= 1) s += __shfl_xor_sync(0xffffffffu, s, o);
    if (lane == 0) sh[wrp] = s;
    __syncthreads();
    if (threadIdx.x == 0) {
        float t = 0.f;
        #pragma unroll
        for (int i = 0; i < 8; i++) t += sh[i];
        sh[0] = rsqrtf(t / (float)DMODEL + 1e-5f);
    }
    __syncthreads();
    float inv = sh[0];
    for (int d = threadIdx.x; d < DMODEL; d += 256) {
        float v = x[d] * inv * w[d];
        __nv_bfloat16 h = __float2bfloat16(v);
        OH[(size_t)r * DMODEL + d] = h;
        OL[(size_t)r * DMODEL + d] = __float2bfloat16(v - __bfloat162float(h));
    }
}

// ---------------- 3xTF32 split mma.sync GEMM (small shapes) -----------------
__device__ __forceinline__ uint32_t f2tf(float f) {
    uint32_t r;
    asm("cvt.rna.tf32.f32 %0, %1;" : "=r"(r) : "f"(f));
    return r;
}
#define KSTR 20

__global__ __launch_bounds__(256) void gemm_tf32s_kernel(
    const float* __restrict__ A, int lda,
    const float* __restrict__ B, int ldb,
    float* __restrict__ C, int ldc,
    int M, int N, int K, int mode, const float* __restrict__ bias)
{
    __shared__ uint32_t Ash[128 * KSTR], Asl[128 * KSTR];
    __shared__ uint32_t Bsh[128 * KSTR], Bsl[128 * KSTR];

    const int tid  = threadIdx.x;
    const int warp = tid >> 5;
    const int lane = tid & 31;
    const int g = lane >> 2, t = lane & 3;
    const int wm = (warp >> 2) * 64;
    const int wn = (warp & 3) * 32;
    const int brow = blockIdx.y * 128;
    const int bcol = blockIdx.x * 128;
    const int gr0 = tid >> 2;
    const int gr1 = (tid + 256) >> 2;
    const int gk  = (tid & 3) * 4;

    float c[4][4][4];
    #pragma unroll
    for (int mi = 0; mi < 4; mi++)
        #pragma unroll
        for (int ni = 0; ni < 4; ni++)
            #pragma unroll
            for (int q = 0; q < 4; q++) c[mi][ni][q] = 0.f;

    const int nk = K / 16;
    float4 aR0, aR1, bR0, bR1;
    const bool bv0 = (bcol + gr0) < N;
    const bool bv1 = (bcol + gr1) < N;

    aR0 = *(const float4*)&A[(size_t)(brow + gr0) * lda + gk];
    aR1 = *(const float4*)&A[(size_t)(brow + gr1) * lda + gk];
    bR0 = bv0 ? *(const float4*)&B[(size_t)(bcol + gr0) * ldb + gk] : make_float4(0,0,0,0);
    bR1 = bv1 ? *(const float4*)&B[(size_t)(bcol + gr1) * ldb + gk] : make_float4(0,0,0,0);

    for (int kt = 0; kt < nk; kt++) {
        __syncthreads();
        #pragma unroll
        for (int q = 0; q < 4; q++) {
            float av0 = (&aR0.x)[q], av1 = (&aR1.x)[q];
            float bw0 = (&bR0.x)[q], bw1 = (&bR1.x)[q];
            uint32_t h;
            h = f2tf(av0); Ash[gr0*KSTR+gk+q] = h; Asl[gr0*KSTR+gk+q] = f2tf(av0 - __uint_as_float(h));
            h = f2tf(av1); Ash[gr1*KSTR+gk+q] = h; Asl[gr1*KSTR+gk+q] = f2tf(av1 - __uint_as_float(h));
            h = f2tf(bw0); Bsh[gr0*KSTR+gk+q] = h; Bsl[gr0*KSTR+gk+q] = f2tf(bw0 - __uint_as_float(h));
            h = f2tf(bw1); Bsh[gr1*KSTR+gk+q] = h; Bsl[gr1*KSTR+gk+q] = f2tf(bw1 - __uint_as_float(h));
        }
        __syncthreads();

        if (kt + 1 < nk) {
            int k0 = (kt + 1) * 16;
            aR0 = *(const float4*)&A[(size_t)(brow + gr0) * lda + k0 + gk];
            aR1 = *(const float4*)&A[(size_t)(brow + gr1) * lda + k0 + gk];
            bR0 = bv0 ? *(const float4*)&B[(size_t)(bcol + gr0) * ldb + k0 + gk] : make_float4(0,0,0,0);
            bR1 = bv1 ? *(const float4*)&B[(size_t)(bcol + gr1) * ldb + k0 + gk] : make_float4(0,0,0,0);
        }

        #pragma unroll
        for (int ks = 0; ks < 16; ks += 8) {
            uint32_t afh[4][4], afl[4][4], bfh[4][2], bfl[4][2];
            #pragma unroll
            for (int mi = 0; mi < 4; mi++) {
                int mr = wm + mi * 16;
                afh[mi][0] = Ash[(mr+g  )*KSTR+ks+t  ]; afl[mi][0] = Asl[(mr+g  )*KSTR+ks+t  ];
                afh[mi][1] = Ash[(mr+g+8)*KSTR+ks+t  ]; afl[mi][1] = Asl[(mr+g+8)*KSTR+ks+t  ];
                afh[mi][2] = Ash[(mr+g  )*KSTR+ks+t+4]; afl[mi][2] = Asl[(mr+g  )*KSTR+ks+t+4];
                afh[mi][3] = Ash[(mr+g+8)*KSTR+ks+t+4]; afl[mi][3] = Asl[(mr+g+8)*KSTR+ks+t+4];
            }
            #pragma unroll
            for (int ni = 0; ni < 4; ni++) {
                int nr = wn + ni * 8;
                bfh[ni][0] = Bsh[(nr+g)*KSTR+ks+t  ]; bfl[ni][0] = Bsl[(nr+g)*KSTR+ks+t  ];
                bfh[ni][1] = Bsh[(nr+g)*KSTR+ks+t+4]; bfl[ni][1] = Bsl[(nr+g)*KSTR+ks+t+4];
            }
            #pragma unroll
            for (int mi = 0; mi < 4; mi++)
                #pragma unroll
                for (int ni = 0; ni < 4; ni++) {
                    #define MMA_TF32(AF, BF) \
                        asm volatile("mma.sync.aligned.m16n8k8.row.col.f32.tf32.tf32.f32 " \
                            "{%0,%1,%2,%3}, {%4,%5,%6,%7}, {%8,%9}, {%0,%1,%2,%3};\n" \
                            : "+f"(c[mi][ni][0]), "+f"(c[mi][ni][1]), \
                              "+f"(c[mi][ni][2]), "+f"(c[mi][ni][3]) \
                            : "r"(AF[mi][0]), "r"(AF[mi][1]), "r"(AF[mi][2]), "r"(AF[mi][3]), \
                              "r"(BF[ni][0]), "r"(BF[ni][1]))
                    MMA_TF32(afh, bfh);
                    MMA_TF32(afh, bfl);
                    MMA_TF32(afl, bfh);
                    #undef MMA_TF32
                }
        }
    }

    #pragma unroll
    for (int mi = 0; mi < 4; mi++) {
        int r0 = brow + wm + mi * 16 + g;
        #pragma unroll
        for (int ni = 0; ni < 4; ni++) {
            int col = bcol + wn + ni * 8 + 2 * t;
            #pragma unroll
            for (int q = 0; q < 4; q++) {
                int rr = r0 + (q >> 1) * 8;
                int cc = col + (q & 1);
                if (cc < N) {
                    size_t idx = (size_t)rr * ldc + cc;
                    float v = c[mi][ni][q];
                    if (mode == 2) {
                        v += bias[cc];
                        v = fmaxf(v, 0.f) + log1pf(expf(-fabsf(v)));
                    }
                    C[idx] = v;
                }
            }
        }
    }
}

// ---------------- depthwise causal conv (k=4) + silu ------------------------
__global__ void conv_silu_kernel(const float* __restrict__ XZ,
                                 const float* __restrict__ cw,
                                 const float* __restrict__ cb,
                                 float* __restrict__ U) {
    int d = blockIdx.x * blockDim.x + threadIdx.x;
    int r = blockIdx.y;
    if (d >= DINNER) return;
    int l = r & (LL - 1);
    float w0 = cw[d*4+0], w1 = cw[d*4+1], w2 = cw[d*4+2], w3 = cw[d*4+3];
    const float* Xp = XZ + (size_t)r * (2 * DINNER) + d;
    float acc = cb[d] + w3 * Xp[0];
    if (l >= 1) acc += w2 * Xp[-(2 * DINNER)];
    if (l >= 2) acc += w1 * Xp[-2 * (2 * DINNER)];
    if (l >= 3) acc += w0 * Xp[-3 * (2 * DINNER)];
    U[(size_t)r * DINNER + d] = acc / (1.f + expf(-acc));
}

// ---------------- selective scan (exp-of-suffix-cumsum formulation) ---------
__global__ void scan_kernel(const float* __restrict__ DT, const float* __restrict__ U,
                            const float* __restrict__ XD, const float* __restrict__ Alog,
                            const float* __restrict__ Dp, const float* __restrict__ XZ,
                            __nv_bfloat16* __restrict__ YH, __nv_bfloat16* __restrict__ YL,
                            float* __restrict__ SC)
{
    int b  = blockIdx.y;
    int n  = threadIdx.x & 15;
    int dl = threadIdx.x >> 4;
    int d  = blockIdx.x * 16 + dl;
    float A = -expf(Alog[d * DSTATE + n]);
    size_t cbase = ((size_t)b * DINNER * DSTATE + (size_t)d * DSTATE + n) * NCHK;

    float S = 0.f;
    for (int l = LL - 1; l >= 0; --l) {
        int r = b * LL + l;
        if ((l & (CHK - 1)) == 0) SC[cbase + (l >> 7)] = S;
        S += DT[(size_t)r * DINNER + d] * A;
    }

    float num = 0.f;
    float Dv = Dp[d];
    S = 0.f;
    for (int l = 0; l < LL; ++l) {
        int r = b * LL + l;
        float dt = DT[(size_t)r * DINNER + d];
        if ((l & (CHK - 1)) == 0) S = SC[cbase + (l >> 7)];
        else S -= dt * A;
        float es = expf(S);
        float u  = U[(size_t)r * DINNER + d];
        float Bm = XD[(size_t)r * XDW + DTRANK + n];
        float Cm = XD[(size_t)r * XDW + DTRANK + DSTATE + n];
        num += dt * u * Bm * es;
        float part = (num / (es + 1e-12f)) * Cm;
        part += __shfl_xor_sync(0xffffffffu, part, 8);
        part += __shfl_xor_sync(0xffffffffu, part, 4);
        part += __shfl_xor_sync(0xffffffffu, part, 2);
        part += __shfl_xor_sync(0xffffffffu, part, 1);
        if (n == 0) {
            float y   = part + u * Dv;
            float res = XZ[(size_t)r * (2 * DINNER) + DINNER + d];
            float yv  = y * (res / (1.f + expf(-res)));
            __nv_bfloat16 h = __float2bfloat16(yv);
            YH[(size_t)r * DINNER + d] = h;
            YL[(size_t)r * DINNER + d] = __float2bfloat16(yv - __bfloat162float(h));
        }
    }
}

// ---------------- driver ----------------------------------------------------
extern "C" void kernel_launch(void* const* d_in, const int* in_sizes, int n_in,
                              void* d_out, int out_size) {
    const int*   ids       = (const int*)  d_in[0];
    const float* emb       = (const float*)d_in[1];
    const float* W_in      = (const float*)d_in[2];
    const float* conv_w    = (const float*)d_in[3];
    const float* conv_b    = (const float*)d_in[4];
    const float* x_proj_w  = (const float*)d_in[5];
    const float* dt_proj_w = (const float*)d_in[6];
    const float* dt_proj_b = (const float*)d_in[7];
    const float* A_log     = (const float*)d_in[8];
    const float* D_param   = (const float*)d_in[9];
    const float* W_out     = (const float*)d_in[10];
    const float* norm_w    = (const float*)d_in[11];
    const float* norm_f_w  = (const float*)d_in[12];
    float* out = (float*)d_out;

    float *pX, *pXZ, *pU, *pXDBL, *pDT, *pSC;
    __nv_bfloat16 *pXNh, *pXNl, *pYh, *pYl, *pEh, *pEl, *pWih, *pWil, *pWoh, *pWol;
    cudaGetSymbolAddress((void**)&pX,    g_X);
    cudaGetSymbolAddress((void**)&pXZ,   g_XZ);
    cudaGetSymbolAddress((void**)&pU,    g_U);
    cudaGetSymbolAddress((void**)&pXDBL, g_XDBL);
    cudaGetSymbolAddress((void**)&pDT,   g_DT);
    cudaGetSymbolAddress((void**)&pSC,   g_SC);
    cudaGetSymbolAddress((void**)&pXNh,  g_XNh);
    cudaGetSymbolAddress((void**)&pXNl,  g_XNl);
    cudaGetSymbolAddress((void**)&pYh,   g_Yh);
    cudaGetSymbolAddress((void**)&pYl,   g_Yl);
    cudaGetSymbolAddress((void**)&pEh,   g_Eh);
    cudaGetSymbolAddress((void**)&pEl,   g_El);
    cudaGetSymbolAddress((void**)&pWih,  g_Wih);
    cudaGetSymbolAddress((void**)&pWil,  g_Wil);
    cudaGetSymbolAddress((void**)&pWoh,  g_Woh);
    cudaGetSymbolAddress((void**)&pWol,  g_Wol);

    static int smem_set = 0;
    if (!smem_set) {
        cudaFuncSetAttribute(gemm_bf16s_kernel,
                             cudaFuncAttributeMaxDynamicSharedMemorySize, GSMEM);
        smem_set = 1;
    }

    // launch order: idx 3 = first gemm_bf16s (W_in layer 0) -> gets profiled
    embed_kernel<<<BL, 256>>>(ids, emb, pX);                                     // 0

    for (int i = 0; i < NLAYER; i++) {
        split_kernel<<<(2 * DINNER * DMODEL / 4 + 255) / 256, 256>>>(            // 1
            W_in + (size_t)i * 2 * DINNER * DMODEL, pWih, pWil, 2 * DINNER * DMODEL / 4);

        rmsnorm_kernel<<<BL, 256>>>(pX, norm_w + (size_t)i * DMODEL, pXNh, pXNl);// 2

        // xz = xn @ W_in^T : (2048,3072) K=768
        gemm_bf16s_kernel<<<dim3(BL / 128, 2 * DINNER / 128), 256, GSMEM>>>(     // 3
            pXNh, pXNl, pWih, pWil, pXZ, 2 * DINNER, DMODEL, 0);

        conv_silu_kernel<<<dim3(DINNER / 256, BL), 256>>>(
            pXZ, conv_w + (size_t)i * DINNER * 4, conv_b + (size_t)i * DINNER, pU);

        // x_dbl = u @ x_proj_w^T : (2048,80) K=1536 — 3xTF32 split
        gemm_tf32s_kernel<<<dim3(1, BL / 128), 256>>>(
            pU, DINNER, x_proj_w + (size_t)i * XDW * DINNER, DINNER,
            pXDBL, XDW, BL, XDW, DINNER, 0, nullptr);

        // dt = softplus(x_dbl[:, :48] @ dt_proj_w^T + b)
        gemm_tf32s_kernel<<<dim3(DINNER / 128, BL / 128), 256>>>(
            pXDBL, XDW, dt_proj_w + (size_t)i * DINNER * DTRANK, DTRANK,
            pDT, DINNER, BL, DINNER, DTRANK, 2, dt_proj_b + (size_t)i * DINNER);

        scan_kernel<<<dim3(DINNER / 16, BB), 256>>>(
            pDT, pU, pXDBL, A_log + (size_t)i * DINNER * DSTATE,
            D_param + (size_t)i * DINNER, pXZ, pYh, pYl, pSC);

        split_kernel<<<(DMODEL * DINNER / 4 + 255) / 256, 256>>>(
            W_out + (size_t)i * DMODEL * DINNER, pWoh, pWol, DMODEL * DINNER / 4);

        // x += y @ W_out^T : (2048,768) K=1536
        gemm_bf16s_kernel<<<dim3(BL / 128, DMODEL / 128), 256, GSMEM>>>(
            pYh, pYl, pWoh, pWol, pX, DMODEL, DINNER, 1);
    }

    rmsnorm_kernel<<<BL, 256>>>(pX, norm_f_w, pXNh, pXNl);

    split_kernel<<<(VOCAB * DMODEL / 4 + 255) / 256, 256>>>(emb, pEh, pEl, VOCAB * DMODEL / 4);

    // logits = xn @ emb^T : (2048,32000) K=768
    gemm_bf16s_kernel<<<dim3(BL / 128, VOCAB / 128), 256, GSMEM>>>(
        pXNh, pXNl, pEh, pEl, out, VOCAB, DMODEL, 0);
}

// round 6
// speedup vs baseline: 1.0587x; 1.0224x over previous
#include <cuda_runtime.h>
#include <cuda_bf16.h>
#include <math.h>
#include <stdint.h>

#define NLAYER 2
#define DMODEL 768
#define VOCAB  32000
#define DSTATE 16
#define DINNER 1536
#define DTRANK 48
#define BB 2
#define LL 1024
#define BL (BB*LL)
#define XDW 80   // DT_RANK + 2*D_STATE
#define CHK 128  // scan checkpoint interval
#define NCHK (LL/CHK)
#define XP_SPLIT 12   // x_proj split-K factor (K chunk = 128)
#define WO_SPLIT 2    // W_out split-K factor (K chunk = 768)

// ---------------- scratch (device globals; no allocation allowed) ----------
__device__ float g_X   [BL*DMODEL];            // residual stream (fp32)
__device__ float g_XZ  [BL*2*DINNER];          // in_proj output
__device__ float g_U   [BL*DINNER];            // silu(conv(xs))
__device__ float g_XDBL[BL*XDW];               // x_proj output (delta|B|C)
__device__ float g_DT  [BL*DINNER];            // softplus(dt)
__device__ float g_SC  [BB*DINNER*DSTATE*NCHK];// scan suffix-sum checkpoints
__device__ float g_XP  [XP_SPLIT*BL*XDW];      // x_proj split-K partials
__device__ float g_PW  [WO_SPLIT*BL*DMODEL];   // W_out split-K partials
// bf16 hi/lo split operands
__device__ __nv_bfloat16 g_XNh[BL*DMODEL],  g_XNl[BL*DMODEL];     // rmsnorm out
__device__ __nv_bfloat16 g_Yh [BL*DINNER],  g_Yl [BL*DINNER];     // scan out
__device__ __nv_bfloat16 g_Eh [VOCAB*DMODEL], g_El[VOCAB*DMODEL]; // embedding
__device__ __nv_bfloat16 g_Wih[2*DINNER*DMODEL], g_Wil[2*DINNER*DMODEL];
__device__ __nv_bfloat16 g_Woh[DMODEL*DINNER],   g_Wol[DMODEL*DINNER];

// ======================= PTX helpers (arch-neutral) =========================
__device__ __forceinline__ uint32_t smem_u32(const void* p) {
    uint32_t a;
    asm("{ .reg .u64 t; cvta.to.shared.u64 t, %1; cvt.u32.u64 %0, t; }"
        : "=r"(a) : "l"(p));
    return a;
}
__device__ __forceinline__ void cp16(uint32_t d, const void* s) {
    asm volatile("cp.async.cg.shared.global [%0], [%1], 16;" :: "r"(d), "l"(s));
}
#define CP_COMMIT() asm volatile("cp.async.commit_group;" ::: "memory")
#define CP_WAIT(N)  asm volatile("cp.async.wait_group %0;" :: "n"(N) : "memory")
#define LDSM4(r, a) \
    asm volatile("ldmatrix.sync.aligned.m8n8.x4.shared.b16 {%0,%1,%2,%3}, [%4];" \
        : "=r"((r)[0]), "=r"((r)[1]), "=r"((r)[2]), "=r"((r)[3]) : "r"(a))
#define MMA16816(d, a, b0, b1) \
    asm volatile("mma.sync.aligned.m16n8k16.row.col.f32.bf16.bf16.f32 " \
        "{%0,%1,%2,%3}, {%4,%5,%6,%7}, {%8,%9}, {%0,%1,%2,%3};" \
        : "+f"((d)[0]), "+f"((d)[1]), "+f"((d)[2]), "+f"((d)[3]) \
        : "r"((a)[0]), "r"((a)[1]), "r"((a)[2]), "r"((a)[3]), "r"(b0), "r"(b1))

// ============ split-bf16 mma.sync GEMM: C[M,N] = A[M,K]*B[N,K]^T ============
// Supports split-K via blockIdx.z: column offset z*K, output offset z*czstride.
// ldk = full row stride of A/B; K = chunk size (mult of 32).
// mode 0: C = acc ; mode 1: C += acc.
#define STAGE_B 32768
#define NSTAGE  3
#define GSMEM   (NSTAGE * STAGE_B)
#define SWZOFF(row, chunk) ((uint32_t)((row) * 64 + ((((chunk) + ((row) >> 1)) & 3) << 4)))

__device__ __forceinline__ void load_tile(
    uint32_t dstb,
    const __nv_bfloat16* __restrict__ Ah, const __nv_bfloat16* __restrict__ Al,
    const __nv_bfloat16* __restrict__ Bh, const __nv_bfloat16* __restrict__ Bl,
    int brow, int bcol, int ldk, int koff, int kc, int tid)
{
    const int row0  = tid >> 2;
    const int chunk = tid & 3;
    const __nv_bfloat16* srcs[4] = {Ah, Al, Bh, Bl};
    const int r0s[4] = {brow, brow, bcol, bcol};
    #pragma unroll
    for (int m = 0; m < 4; m++) {
        #pragma unroll
        for (int i = 0; i < 2; i++) {
            int row = row0 + i * 64;
            const void* src = srcs[m] + (size_t)(r0s[m] + row) * ldk + koff + kc * 32 + chunk * 8;
            cp16(dstb + m * 8192 + SWZOFF(row, chunk), src);
        }
    }
}

__global__ __launch_bounds__(256, 2) void gemm_bf16s_kernel(
    const __nv_bfloat16* __restrict__ Ah, const __nv_bfloat16* __restrict__ Al,
    const __nv_bfloat16* __restrict__ Bh, const __nv_bfloat16* __restrict__ Bl,
    float* __restrict__ C, int ldc, int ldk, int K, int mode, size_t czstride)
{
    extern __shared__ char smem[];
    const uint32_t sbase = smem_u32(smem);
    const int tid  = threadIdx.x;
    const int warp = tid >> 5, lane = tid & 31;
    const int brow = blockIdx.x * 128;
    const int bcol = blockIdx.y * 128;
    const int koff = blockIdx.z * K;
    C += (size_t)blockIdx.z * czstride;
    const int wm = (warp >> 2) * 64;
    const int wn = (warp & 3) * 32;

    float acc[4][4][4];
    #pragma unroll
    for (int mi = 0; mi < 4; mi++)
        #pragma unroll
        for (int ni = 0; ni < 4; ni++)
            #pragma unroll
            for (int q = 0; q < 4; q++) acc[mi][ni][q] = 0.f;

    const int nk = K >> 5;

    load_tile(sbase, Ah, Al, Bh, Bl, brow, bcol, ldk, koff, 0, tid);
    CP_COMMIT();
    if (nk > 1)
        load_tile(sbase + STAGE_B, Ah, Al, Bh, Bl, brow, bcol, ldk, koff, 1, tid);
    CP_COMMIT();

    const int a_row = lane & 15;
    const int a_kc  = lane >> 4;
    const int b_row = (lane & 7) + ((lane >> 4) << 3);
    const int b_kc  = (lane >> 3) & 1;

    int stg = 0, stg2 = 2;
    for (int c = 0; c < nk; c++) {
        CP_WAIT(1);
        __syncthreads();

        const uint32_t tb = sbase + stg * STAGE_B;
        #pragma unroll
        for (int s = 0; s < 2; s++) {
            uint32_t bh[2][4], bl[2][4];
            #pragma unroll
            for (int p = 0; p < 2; p++) {
                int row = wn + p * 16 + b_row;
                uint32_t a = tb + 16384 + SWZOFF(row, 2 * s + b_kc);
                LDSM4(bh[p], a);
                LDSM4(bl[p], a + 8192);
            }
            #pragma unroll
            for (int mi = 0; mi < 4; mi++) {
                uint32_t ah[4], al[4];
                int row = wm + mi * 16 + a_row;
                uint32_t a = tb + SWZOFF(row, 2 * s + a_kc);
                LDSM4(ah, a);
                LDSM4(al, a + 8192);
                #pragma unroll
                for (int ni = 0; ni < 4; ni++) {
                    const int p = ni >> 1, sb = (ni & 1) * 2;
                    MMA16816(acc[mi][ni], ah, bh[p][sb], bh[p][sb + 1]);
                    MMA16816(acc[mi][ni], ah, bl[p][sb], bl[p][sb + 1]);
                    MMA16816(acc[mi][ni], al, bh[p][sb], bh[p][sb + 1]);
                }
            }
        }

        if (c + 2 < nk)
            load_tile(sbase + stg2 * STAGE_B, Ah, Al, Bh, Bl, brow, bcol, ldk, koff, c + 2, tid);
        CP_COMMIT();

        stg  = (stg  == 2) ? 0 : stg  + 1;
        stg2 = (stg2 == 2) ? 0 : stg2 + 1;
    }

    const int g = lane >> 2, t = lane & 3;
    #pragma unroll
    for (int mi = 0; mi < 4; mi++) {
        int row0 = brow + wm + mi * 16 + g;
        #pragma unroll
        for (int ni = 0; ni < 4; ni++) {
            int col = bcol + wn + ni * 8 + 2 * t;
            float2* p0 = (float2*)(C + (size_t)row0 * ldc + col);
            float2* p1 = (float2*)(C + (size_t)(row0 + 8) * ldc + col);
            if (mode == 1) {
                float2 o0 = *p0, o1 = *p1;
                o0.x += acc[mi][ni][0]; o0.y += acc[mi][ni][1];
                o1.x += acc[mi][ni][2]; o1.y += acc[mi][ni][3];
                *p0 = o0; *p1 = o1;
            } else {
                *p0 = make_float2(acc[mi][ni][0], acc[mi][ni][1]);
                *p1 = make_float2(acc[mi][ni][2], acc[mi][ni][3]);
            }
        }
    }
}

// ---------------- split-K reduce kernels -------------------------------------
__global__ void reduce_xp_kernel(const float* __restrict__ P, float* __restrict__ O) {
    int i = blockIdx.x * blockDim.x + threadIdx.x;      // over BL*XDW/4
    if (i >= BL * XDW / 4) return;
    float4 s = ((const float4*)P)[i];
    #pragma unroll
    for (int z = 1; z < XP_SPLIT; z++) {
        float4 v = ((const float4*)(P + (size_t)z * BL * XDW))[i];
        s.x += v.x; s.y += v.y; s.z += v.z; s.w += v.w;
    }
    ((float4*)O)[i] = s;
}
__global__ void reduce_pw_kernel(const float* __restrict__ P, float* __restrict__ X) {
    int i = blockIdx.x * blockDim.x + threadIdx.x;      // over BL*DMODEL/4
    if (i >= BL * DMODEL / 4) return;
    float4 a = ((const float4*)P)[i];
    float4 b = ((const float4*)(P + (size_t)BL * DMODEL))[i];
    float4 x = ((float4*)X)[i];
    x.x += a.x + b.x; x.y += a.y + b.y; x.z += a.z + b.z; x.w += a.w + b.w;
    ((float4*)X)[i] = x;
}

// ---------------- fp32 -> bf16 hi/lo split (weights) ------------------------
__global__ void split_kernel(const float* __restrict__ S,
                             __nv_bfloat16* __restrict__ H,
                             __nv_bfloat16* __restrict__ L, int n4) {
    int i = blockIdx.x * blockDim.x + threadIdx.x;
    if (i >= n4) return;
    float4 v = ((const float4*)S)[i];
    __nv_bfloat16 h0 = __float2bfloat16(v.x), h1 = __float2bfloat16(v.y);
    __nv_bfloat16 h2 = __float2bfloat16(v.z), h3 = __float2bfloat16(v.w);
    __nv_bfloat16 l0 = __float2bfloat16(v.x - __bfloat162float(h0));
    __nv_bfloat16 l1 = __float2bfloat16(v.y - __bfloat162float(h1));
    __nv_bfloat16 l2 = __float2bfloat16(v.z - __bfloat162float(h2));
    __nv_bfloat16 l3 = __float2bfloat16(v.w - __bfloat162float(h3));
    __nv_bfloat162 a; a.x = h0; a.y = h1;
    __nv_bfloat162 b; b.x = h2; b.y = h3;
    ((__nv_bfloat162*)H)[i * 2] = a; ((__nv_bfloat162*)H)[i * 2 + 1] = b;
    a.x = l0; a.y = l1; b.x = l2; b.y = l3;
    ((__nv_bfloat162*)L)[i * 2] = a; ((__nv_bfloat162*)L)[i * 2 + 1] = b;
}

// ---------------- embedding gather -----------------------------------------
__global__ void embed_kernel(const int* __restrict__ ids,
                             const float* __restrict__ emb,
                             float* __restrict__ X) {
    int r = blockIdx.x;
    int id = ids[r];
    const float* src = emb + (size_t)id * DMODEL;
    float* dst = X + (size_t)r * DMODEL;
    for (int d = threadIdx.x; d < DMODEL; d += blockDim.x) dst[d] = src[d];
}

// ---------------- rmsnorm (fused bf16 hi/lo split output) -------------------
__global__ void rmsnorm_kernel(const float* __restrict__ X,
                               const float* __restrict__ w,
                               __nv_bfloat16* __restrict__ OH,
                               __nv_bfloat16* __restrict__ OL) {
    int r = blockIdx.x;
    const float* x = X + (size_t)r * DMODEL;
    float s = 0.f;
    for (int d = threadIdx.x; d < DMODEL; d += 256) { float v = x[d]; s += v * v; }
    __shared__ float sh[8];
    int lane = threadIdx.x & 31, wrp = threadIdx.x >> 5;
    #pragma unroll
    for (int o = 16; o > 0; o >>= 1) s += __shfl_xor_sync(0xffffffffu, s, o);
    if (lane == 0) sh[wrp] = s;
    __syncthreads();
    if (threadIdx.x == 0) {
        float t = 0.f;
        #pragma unroll
        for (int i = 0; i < 8; i++) t += sh[i];
        sh[0] = rsqrtf(t / (float)DMODEL + 1e-5f);
    }
    __syncthreads();
    float inv = sh[0];
    for (int d = threadIdx.x; d < DMODEL; d += 256) {
        float v = x[d] * inv * w[d];
        __nv_bfloat16 h = __float2bfloat16(v);
        OH[(size_t)r * DMODEL + d] = h;
        OL[(size_t)r * DMODEL + d] = __float2bfloat16(v - __bfloat162float(h));
    }
}

// ---------------- 3xTF32 split mma.sync GEMM (small shapes, split-K) --------
// mode 0: C = acc ; mode 2: C = softplus(acc + bias[col])
__device__ __forceinline__ uint32_t f2tf(float f) {
    uint32_t r;
    asm("cvt.rna.tf32.f32 %0, %1;" : "=r"(r) : "f"(f));
    return r;
}
#define KSTR 20

__global__ __launch_bounds__(256) void gemm_tf32s_kernel(
    const float* __restrict__ A, int lda,
    const float* __restrict__ B, int ldb,
    float* __restrict__ C, int ldc,
    int M, int N, int K, int mode, const float* __restrict__ bias, size_t czstride)
{
    __shared__ uint32_t Ash[128 * KSTR], Asl[128 * KSTR];
    __shared__ uint32_t Bsh[128 * KSTR], Bsl[128 * KSTR];

    const int tid  = threadIdx.x;
    const int warp = tid >> 5;
    const int lane = tid & 31;
    const int g = lane >> 2, t = lane & 3;
    const int wm = (warp >> 2) * 64;
    const int wn = (warp & 3) * 32;
    const int brow = blockIdx.y * 128;
    const int bcol = blockIdx.x * 128;
    const int koff = blockIdx.z * K;
    C += (size_t)blockIdx.z * czstride;
    const int gr0 = tid >> 2;
    const int gr1 = (tid + 256) >> 2;
    const int gk  = (tid & 3) * 4;

    float c[4][4][4];
    #pragma unroll
    for (int mi = 0; mi < 4; mi++)
        #pragma unroll
        for (int ni = 0; ni < 4; ni++)
            #pragma unroll
            for (int q = 0; q < 4; q++) c[mi][ni][q] = 0.f;

    const int nk = K / 16;
    float4 aR0, aR1, bR0, bR1;
    const bool bv0 = (bcol + gr0) < N;
    const bool bv1 = (bcol + gr1) < N;

    aR0 = *(const float4*)&A[(size_t)(brow + gr0) * lda + koff + gk];
    aR1 = *(const float4*)&A[(size_t)(brow + gr1) * lda + koff + gk];
    bR0 = bv0 ? *(const float4*)&B[(size_t)(bcol + gr0) * ldb + koff + gk] : make_float4(0,0,0,0);
    bR1 = bv1 ? *(const float4*)&B[(size_t)(bcol + gr1) * ldb + koff + gk] : make_float4(0,0,0,0);

    for (int kt = 0; kt < nk; kt++) {
        __syncthreads();
        #pragma unroll
        for (int q = 0; q < 4; q++) {
            float av0 = (&aR0.x)[q], av1 = (&aR1.x)[q];
            float bw0 = (&bR0.x)[q], bw1 = (&bR1.x)[q];
            uint32_t h;
            h = f2tf(av0); Ash[gr0*KSTR+gk+q] = h; Asl[gr0*KSTR+gk+q] = f2tf(av0 - __uint_as_float(h));
            h = f2tf(av1); Ash[gr1*KSTR+gk+q] = h; Asl[gr1*KSTR+gk+q] = f2tf(av1 - __uint_as_float(h));
            h = f2tf(bw0); Bsh[gr0*KSTR+gk+q] = h; Bsl[gr0*KSTR+gk+q] = f2tf(bw0 - __uint_as_float(h));
            h = f2tf(bw1); Bsh[gr1*KSTR+gk+q] = h; Bsl[gr1*KSTR+gk+q] = f2tf(bw1 - __uint_as_float(h));
        }
        __syncthreads();

        if (kt + 1 < nk) {
            int k0 = koff + (kt + 1) * 16;
            aR0 = *(const float4*)&A[(size_t)(brow + gr0) * lda + k0 + gk];
            aR1 = *(const float4*)&A[(size_t)(brow + gr1) * lda + k0 + gk];
            bR0 = bv0 ? *(const float4*)&B[(size_t)(bcol + gr0) * ldb + k0 + gk] : make_float4(0,0,0,0);
            bR1 = bv1 ? *(const float4*)&B[(size_t)(bcol + gr1) * ldb + k0 + gk] : make_float4(0,0,0,0);
        }

        #pragma unroll
        for (int ks = 0; ks < 16; ks += 8) {
            uint32_t afh[4][4], afl[4][4], bfh[4][2], bfl[4][2];
            #pragma unroll
            for (int mi = 0; mi < 4; mi++) {
                int mr = wm + mi * 16;
                afh[mi][0] = Ash[(mr+g  )*KSTR+ks+t  ]; afl[mi][0] = Asl[(mr+g  )*KSTR+ks+t  ];
                afh[mi][1] = Ash[(mr+g+8)*KSTR+ks+t  ]; afl[mi][1] = Asl[(mr+g+8)*KSTR+ks+t  ];
                afh[mi][2] = Ash[(mr+g  )*KSTR+ks+t+4]; afl[mi][2] = Asl[(mr+g  )*KSTR+ks+t+4];
                afh[mi][3] = Ash[(mr+g+8)*KSTR+ks+t+4]; afl[mi][3] = Asl[(mr+g+8)*KSTR+ks+t+4];
            }
            #pragma unroll
            for (int ni = 0; ni < 4; ni++) {
                int nr = wn + ni * 8;
                bfh[ni][0] = Bsh[(nr+g)*KSTR+ks+t  ]; bfl[ni][0] = Bsl[(nr+g)*KSTR+ks+t  ];
                bfh[ni][1] = Bsh[(nr+g)*KSTR+ks+t+4]; bfl[ni][1] = Bsl[(nr+g)*KSTR+ks+t+4];
            }
            #pragma unroll
            for (int mi = 0; mi < 4; mi++)
                #pragma unroll
                for (int ni = 0; ni < 4; ni++) {
                    #define MMA_TF32(AF, BF) \
                        asm volatile("mma.sync.aligned.m16n8k8.row.col.f32.tf32.tf32.f32 " \
                            "{%0,%1,%2,%3}, {%4,%5,%6,%7}, {%8,%9}, {%0,%1,%2,%3};\n" \
                            : "+f"(c[mi][ni][0]), "+f"(c[mi][ni][1]), \
                              "+f"(c[mi][ni][2]), "+f"(c[mi][ni][3]) \
                            : "r"(AF[mi][0]), "r"(AF[mi][1]), "r"(AF[mi][2]), "r"(AF[mi][3]), \
                              "r"(BF[ni][0]), "r"(BF[ni][1]))
                    MMA_TF32(afh, bfh);
                    MMA_TF32(afh, bfl);
                    MMA_TF32(afl, bfh);
                    #undef MMA_TF32
                }
        }
    }

    #pragma unroll
    for (int mi = 0; mi < 4; mi++) {
        int r0 = brow + wm + mi * 16 + g;
        #pragma unroll
        for (int ni = 0; ni < 4; ni++) {
            int col = bcol + wn + ni * 8 + 2 * t;
            #pragma unroll
            for (int q = 0; q < 4; q++) {
                int rr = r0 + (q >> 1) * 8;
                int cc = col + (q & 1);
                if (cc < N) {
                    size_t idx = (size_t)rr * ldc + cc;
                    float v = c[mi][ni][q];
                    if (mode == 2) {
                        v += bias[cc];
                        v = fmaxf(v, 0.f) + log1pf(expf(-fabsf(v)));
                    }
                    C[idx] = v;
                }
            }
        }
    }
}

// ---------------- depthwise causal conv (k=4) + silu ------------------------
__global__ void conv_silu_kernel(const float* __restrict__ XZ,
                                 const float* __restrict__ cw,
                                 const float* __restrict__ cb,
                                 float* __restrict__ U) {
    int d = blockIdx.x * blockDim.x + threadIdx.x;
    int r = blockIdx.y;
    if (d >= DINNER) return;
    int l = r & (LL - 1);
    float w0 = cw[d*4+0], w1 = cw[d*4+1], w2 = cw[d*4+2], w3 = cw[d*4+3];
    const float* Xp = XZ + (size_t)r * (2 * DINNER) + d;
    float acc = cb[d] + w3 * Xp[0];
    if (l >= 1) acc += w2 * Xp[-(2 * DINNER)];
    if (l >= 2) acc += w1 * Xp[-2 * (2 * DINNER)];
    if (l >= 3) acc += w0 * Xp[-3 * (2 * DINNER)];
    U[(size_t)r * DINNER + d] = acc / (1.f + expf(-acc));
}

// ---------------- selective scan (exp-of-suffix-cumsum formulation) ---------
__global__ void scan_kernel(const float* __restrict__ DT, const float* __restrict__ U,
                            const float* __restrict__ XD, const float* __restrict__ Alog,
                            const float* __restrict__ Dp, const float* __restrict__ XZ,
                            __nv_bfloat16* __restrict__ YH, __nv_bfloat16* __restrict__ YL,
                            float* __restrict__ SC)
{
    int b  = blockIdx.y;
    int n  = threadIdx.x & 15;
    int dl = threadIdx.x >> 4;
    int d  = blockIdx.x * 16 + dl;
    float A = -expf(Alog[d * DSTATE + n]);
    size_t cbase = ((size_t)b * DINNER * DSTATE + (size_t)d * DSTATE + n) * NCHK;

    float S = 0.f;
    for (int l = LL - 1; l >= 0; --l) {
        int r = b * LL + l;
        if ((l & (CHK - 1)) == 0) SC[cbase + (l >> 7)] = S;
        S += DT[(size_t)r * DINNER + d] * A;
    }

    float num = 0.f;
    float Dv = Dp[d];
    S = 0.f;
    for (int l = 0; l < LL; ++l) {
        int r = b * LL + l;
        float dt = DT[(size_t)r * DINNER + d];
        if ((l & (CHK - 1)) == 0) S = SC[cbase + (l >> 7)];
        else S -= dt * A;
        float es = expf(S);
        float u  = U[(size_t)r * DINNER + d];
        float Bm = XD[(size_t)r * XDW + DTRANK + n];
        float Cm = XD[(size_t)r * XDW + DTRANK + DSTATE + n];
        num += dt * u * Bm * es;
        float part = (num / (es + 1e-12f)) * Cm;
        part += __shfl_xor_sync(0xffffffffu, part, 8);
        part += __shfl_xor_sync(0xffffffffu, part, 4);
        part += __shfl_xor_sync(0xffffffffu, part, 2);
        part += __shfl_xor_sync(0xffffffffu, part, 1);
        if (n == 0) {
            float y   = part + u * Dv;
            float res = XZ[(size_t)r * (2 * DINNER) + DINNER + d];
            float yv  = y * (res / (1.f + expf(-res)));
            __nv_bfloat16 h = __float2bfloat16(yv);
            YH[(size_t)r * DINNER + d] = h;
            YL[(size_t)r * DINNER + d] = __float2bfloat16(yv - __bfloat162float(h));
        }
    }
}

// ---------------- driver ----------------------------------------------------
extern "C" void kernel_launch(void* const* d_in, const int* in_sizes, int n_in,
                              void* d_out, int out_size) {
    const int*   ids       = (const int*)  d_in[0];
    const float* emb       = (const float*)d_in[1];
    const float* W_in      = (const float*)d_in[2];
    const float* conv_w    = (const float*)d_in[3];
    const float* conv_b    = (const float*)d_in[4];
    const float* x_proj_w  = (const float*)d_in[5];
    const float* dt_proj_w = (const float*)d_in[6];
    const float* dt_proj_b = (const float*)d_in[7];
    const float* A_log     = (const float*)d_in[8];
    const float* D_param   = (const float*)d_in[9];
    const float* W_out     = (const float*)d_in[10];
    const float* norm_w    = (const float*)d_in[11];
    const float* norm_f_w  = (const float*)d_in[12];
    float* out = (float*)d_out;

    float *pX, *pXZ, *pU, *pXDBL, *pDT, *pSC, *pXP, *pPW;
    __nv_bfloat16 *pXNh, *pXNl, *pYh, *pYl, *pEh, *pEl, *pWih, *pWil, *pWoh, *pWol;
    cudaGetSymbolAddress((void**)&pX,    g_X);
    cudaGetSymbolAddress((void**)&pXZ,   g_XZ);
    cudaGetSymbolAddress((void**)&pU,    g_U);
    cudaGetSymbolAddress((void**)&pXDBL, g_XDBL);
    cudaGetSymbolAddress((void**)&pDT,   g_DT);
    cudaGetSymbolAddress((void**)&pSC,   g_SC);
    cudaGetSymbolAddress((void**)&pXP,   g_XP);
    cudaGetSymbolAddress((void**)&pPW,   g_PW);
    cudaGetSymbolAddress((void**)&pXNh,  g_XNh);
    cudaGetSymbolAddress((void**)&pXNl,  g_XNl);
    cudaGetSymbolAddress((void**)&pYh,   g_Yh);
    cudaGetSymbolAddress((void**)&pYl,   g_Yl);
    cudaGetSymbolAddress((void**)&pEh,   g_Eh);
    cudaGetSymbolAddress((void**)&pEl,   g_El);
    cudaGetSymbolAddress((void**)&pWih,  g_Wih);
    cudaGetSymbolAddress((void**)&pWil,  g_Wil);
    cudaGetSymbolAddress((void**)&pWoh,  g_Woh);
    cudaGetSymbolAddress((void**)&pWol,  g_Wol);

    static int smem_set = 0;
    if (!smem_set) {
        cudaFuncSetAttribute(gemm_bf16s_kernel,
                             cudaFuncAttributeMaxDynamicSharedMemorySize, GSMEM);
        smem_set = 1;
    }

    embed_kernel<<<BL, 256>>>(ids, emb, pX);                                     // 0

    for (int i = 0; i < NLAYER; i++) {
        split_kernel<<<(2 * DINNER * DMODEL / 4 + 255) / 256, 256>>>(            // 1
            W_in + (size_t)i * 2 * DINNER * DMODEL, pWih, pWil, 2 * DINNER * DMODEL / 4);

        rmsnorm_kernel<<<BL, 256>>>(pX, norm_w + (size_t)i * DMODEL, pXNh, pXNl);// 2

        // xz = xn @ W_in^T : (2048,3072) K=768
        gemm_bf16s_kernel<<<dim3(BL / 128, 2 * DINNER / 128, 1), 256, GSMEM>>>(  // 3
            pXNh, pXNl, pWih, pWil, pXZ, 2 * DINNER, DMODEL, DMODEL, 0, 0);

        conv_silu_kernel<<<dim3(DINNER / 256, BL), 256>>>(
            pXZ, conv_w + (size_t)i * DINNER * 4, conv_b + (size_t)i * DINNER, pU);

        // x_dbl = u @ x_proj_w^T : (2048,80) K=1536, split-K=12 -> partials
        gemm_tf32s_kernel<<<dim3(1, BL / 128, XP_SPLIT), 256>>>(
            pU, DINNER, x_proj_w + (size_t)i * XDW * DINNER, DINNER,
            pXP, XDW, BL, XDW, DINNER / XP_SPLIT, 0, nullptr, (size_t)BL * XDW);
        reduce_xp_kernel<<<(BL * XDW / 4 + 255) / 256, 256>>>(pXP, pXDBL);

        // dt = softplus(x_dbl[:, :48] @ dt_proj_w^T + b)
        gemm_tf32s_kernel<<<dim3(DINNER / 128, BL / 128, 1), 256>>>(
            pXDBL, XDW, dt_proj_w + (size_t)i * DINNER * DTRANK, DTRANK,
            pDT, DINNER, BL, DINNER, DTRANK, 2, dt_proj_b + (size_t)i * DINNER, 0);

        scan_kernel<<<dim3(DINNER / 16, BB), 256>>>(
            pDT, pU, pXDBL, A_log + (size_t)i * DINNER * DSTATE,
            D_param + (size_t)i * DINNER, pXZ, pYh, pYl, pSC);

        split_kernel<<<(DMODEL * DINNER / 4 + 255) / 256, 256>>>(
            W_out + (size_t)i * DMODEL * DINNER, pWoh, pWol, DMODEL * DINNER / 4);

        // y @ W_out^T : (2048,768) K=1536, split-K=2 -> partials, then add to X
        gemm_bf16s_kernel<<<dim3(BL / 128, DMODEL / 128, WO_SPLIT), 256, GSMEM>>>(
            pYh, pYl, pWoh, pWol, pPW, DMODEL, DINNER, DINNER / WO_SPLIT, 0,
            (size_t)BL * DMODEL);
        reduce_pw_kernel<<<(BL * DMODEL / 4 + 255) / 256, 256>>>(pPW, pX);
    }

    rmsnorm_kernel<<<BL, 256>>>(pX, norm_f_w, pXNh, pXNl);

    split_kernel<<<(VOCAB * DMODEL / 4 + 255) / 256, 256>>>(emb, pEh, pEl, VOCAB * DMODEL / 4);

    // logits = xn @ emb^T : (2048,32000) K=768
    gemm_bf16s_kernel<<<dim3(BL / 128, VOCAB / 128, 1), 256, GSMEM>>>(
        pXNh, pXNl, pEh, pEl, out, VOCAB, DMODEL, DMODEL, 0, 0);
}

// round 7
// speedup vs baseline: 1.0925x; 1.0320x over previous
#include <cuda_runtime.h>
#include <cuda_bf16.h>
#include <math.h>
#include <stdint.h>

#define NLAYER 2
#define DMODEL 768
#define VOCAB  32000
#define DSTATE 16
#define DINNER 1536
#define DTRANK 48
#define BB 2
#define LL 1024
#define BL (BB*LL)
#define XDW 80   // DT_RANK + 2*D_STATE
#define CHK 128  // scan checkpoint interval
#define NCHK (LL/CHK)
#define XP_SPLIT 12   // x_proj split-K factor (K chunk = 128)
#define WO_SPLIT 2    // W_out split-K factor (K chunk = 768)

// ---------------- scratch (device globals; no allocation allowed) ----------
__device__ float g_X   [BL*DMODEL];            // residual stream (fp32)
__device__ float g_XZ  [BL*2*DINNER];          // in_proj output
__device__ float g_U   [BL*DINNER];            // silu(conv(xs))
__device__ float g_XDBL[BL*XDW];               // x_proj output (delta|B|C)
__device__ float g_DT  [BL*DINNER];            // softplus(dt)
__device__ float g_SC  [BB*DINNER*DSTATE*NCHK];// scan suffix-sum checkpoints
__device__ float g_XP  [XP_SPLIT*BL*XDW];      // x_proj split-K partials
__device__ float g_PW  [WO_SPLIT*BL*DMODEL];   // W_out split-K partials
// bf16 hi/lo split operands
__device__ __nv_bfloat16 g_XNh[BL*DMODEL],  g_XNl[BL*DMODEL];     // rmsnorm out
__device__ __nv_bfloat16 g_Yh [BL*DINNER],  g_Yl [BL*DINNER];     // scan out
__device__ __nv_bfloat16 g_Eh [VOCAB*DMODEL], g_El[VOCAB*DMODEL]; // embedding
__device__ __nv_bfloat16 g_Wih[2*DINNER*DMODEL], g_Wil[2*DINNER*DMODEL];
__device__ __nv_bfloat16 g_Woh[DMODEL*DINNER],   g_Wol[DMODEL*DINNER];

// ======================= PTX helpers (arch-neutral) =========================
__device__ __forceinline__ uint32_t smem_u32(const void* p) {
    uint32_t a;
    asm("{ .reg .u64 t; cvta.to.shared.u64 t, %1; cvt.u32.u64 %0, t; }"
        : "=r"(a) : "l"(p));
    return a;
}
__device__ __forceinline__ void cp16(uint32_t d, const void* s) {
    asm volatile("cp.async.cg.shared.global [%0], [%1], 16;" :: "r"(d), "l"(s));
}
#define CP_COMMIT() asm volatile("cp.async.commit_group;" ::: "memory")
#define CP_WAIT(N)  asm volatile("cp.async.wait_group %0;" :: "n"(N) : "memory")
#define LDSM4(r, a) \
    asm volatile("ldmatrix.sync.aligned.m8n8.x4.shared.b16 {%0,%1,%2,%3}, [%4];" \
        : "=r"((r)[0]), "=r"((r)[1]), "=r"((r)[2]), "=r"((r)[3]) : "r"(a))
#define MMA16816(d, a, b0, b1) \
    asm volatile("mma.sync.aligned.m16n8k16.row.col.f32.bf16.bf16.f32 " \
        "{%0,%1,%2,%3}, {%4,%5,%6,%7}, {%8,%9}, {%0,%1,%2,%3};" \
        : "+f"((d)[0]), "+f"((d)[1]), "+f"((d)[2]), "+f"((d)[3]) \
        : "r"((a)[0]), "r"((a)[1]), "r"((a)[2]), "r"((a)[3]), "r"(b0), "r"(b1))

// ============ split-bf16 mma.sync GEMM: C[M,N] = A[M,K]*B[N,K]^T ============
// Supports split-K via blockIdx.z: column offset z*K, output offset z*czstride.
// ldk = full row stride of A/B; K = chunk size (mult of 32).
// mode 0: C = acc ; mode 1: C += acc.
#define STAGE_B 32768
#define NSTAGE  3
#define GSMEM   (NSTAGE * STAGE_B)
#define SWZOFF(row, chunk) ((uint32_t)((row) * 64 + ((((chunk) + ((row) >> 1)) & 3) << 4)))

__device__ __forceinline__ void load_tile(
    uint32_t dstb,
    const __nv_bfloat16* __restrict__ Ah, const __nv_bfloat16* __restrict__ Al,
    const __nv_bfloat16* __restrict__ Bh, const __nv_bfloat16* __restrict__ Bl,
    int brow, int bcol, int ldk, int koff, int kc, int tid)
{
    const int row0  = tid >> 2;
    const int chunk = tid & 3;
    const __nv_bfloat16* srcs[4] = {Ah, Al, Bh, Bl};
    const int r0s[4] = {brow, brow, bcol, bcol};
    #pragma unroll
    for (int m = 0; m < 4; m++) {
        #pragma unroll
        for (int i = 0; i < 2; i++) {
            int row = row0 + i * 64;
            const void* src = srcs[m] + (size_t)(r0s[m] + row) * ldk + koff + kc * 32 + chunk * 8;
            cp16(dstb + m * 8192 + SWZOFF(row, chunk), src);
        }
    }
}

__global__ __launch_bounds__(256, 2) void gemm_bf16s_kernel(
    const __nv_bfloat16* __restrict__ Ah, const __nv_bfloat16* __restrict__ Al,
    const __nv_bfloat16* __restrict__ Bh, const __nv_bfloat16* __restrict__ Bl,
    float* __restrict__ C, int ldc, int ldk, int K, int mode, size_t czstride)
{
    extern __shared__ char smem[];
    const uint32_t sbase = smem_u32(smem);
    const int tid  = threadIdx.x;
    const int warp = tid >> 5, lane = tid & 31;
    const int brow = blockIdx.x * 128;
    const int bcol = blockIdx.y * 128;
    const int koff = blockIdx.z * K;
    C += (size_t)blockIdx.z * czstride;
    const int wm = (warp >> 2) * 64;
    const int wn = (warp & 3) * 32;

    float acc[4][4][4];
    #pragma unroll
    for (int mi = 0; mi < 4; mi++)
        #pragma unroll
        for (int ni = 0; ni < 4; ni++)
            #pragma unroll
            for (int q = 0; q < 4; q++) acc[mi][ni][q] = 0.f;

    const int nk = K >> 5;

    load_tile(sbase, Ah, Al, Bh, Bl, brow, bcol, ldk, koff, 0, tid);
    CP_COMMIT();
    if (nk > 1)
        load_tile(sbase + STAGE_B, Ah, Al, Bh, Bl, brow, bcol, ldk, koff, 1, tid);
    CP_COMMIT();

    const int a_row = lane & 15;
    const int a_kc  = lane >> 4;
    const int b_row = (lane & 7) + ((lane >> 4) << 3);
    const int b_kc  = (lane >> 3) & 1;

    int stg = 0, stg2 = 2;
    for (int c = 0; c < nk; c++) {
        CP_WAIT(1);
        __syncthreads();

        const uint32_t tb = sbase + stg * STAGE_B;
        #pragma unroll
        for (int s = 0; s < 2; s++) {
            uint32_t bh[2][4], bl[2][4];
            #pragma unroll
            for (int p = 0; p < 2; p++) {
                int row = wn + p * 16 + b_row;
                uint32_t a = tb + 16384 + SWZOFF(row, 2 * s + b_kc);
                LDSM4(bh[p], a);
                LDSM4(bl[p], a + 8192);
            }
            #pragma unroll
            for (int mi = 0; mi < 4; mi++) {
                uint32_t ah[4], al[4];
                int row = wm + mi * 16 + a_row;
                uint32_t a = tb + SWZOFF(row, 2 * s + a_kc);
                LDSM4(ah, a);
                LDSM4(al, a + 8192);
                #pragma unroll
                for (int ni = 0; ni < 4; ni++) {
                    const int p = ni >> 1, sb = (ni & 1) * 2;
                    MMA16816(acc[mi][ni], ah, bh[p][sb], bh[p][sb + 1]);
                    MMA16816(acc[mi][ni], ah, bl[p][sb], bl[p][sb + 1]);
                    MMA16816(acc[mi][ni], al, bh[p][sb], bh[p][sb + 1]);
                }
            }
        }

        if (c + 2 < nk)
            load_tile(sbase + stg2 * STAGE_B, Ah, Al, Bh, Bl, brow, bcol, ldk, koff, c + 2, tid);
        CP_COMMIT();

        stg  = (stg  == 2) ? 0 : stg  + 1;
        stg2 = (stg2 == 2) ? 0 : stg2 + 1;
    }

    const int g = lane >> 2, t = lane & 3;
    #pragma unroll
    for (int mi = 0; mi < 4; mi++) {
        int row0 = brow + wm + mi * 16 + g;
        #pragma unroll
        for (int ni = 0; ni < 4; ni++) {
            int col = bcol + wn + ni * 8 + 2 * t;
            float2* p0 = (float2*)(C + (size_t)row0 * ldc + col);
            float2* p1 = (float2*)(C + (size_t)(row0 + 8) * ldc + col);
            if (mode == 1) {
                float2 o0 = *p0, o1 = *p1;
                o0.x += acc[mi][ni][0]; o0.y += acc[mi][ni][1];
                o1.x += acc[mi][ni][2]; o1.y += acc[mi][ni][3];
                *p0 = o0; *p1 = o1;
            } else {
                *p0 = make_float2(acc[mi][ni][0], acc[mi][ni][1]);
                *p1 = make_float2(acc[mi][ni][2], acc[mi][ni][3]);
            }
        }
    }
}

// ---------------- split-K reduce kernels -------------------------------------
__global__ void reduce_xp_kernel(const float* __restrict__ P, float* __restrict__ O) {
    int i = blockIdx.x * blockDim.x + threadIdx.x;      // over BL*XDW/4
    if (i >= BL * XDW / 4) return;
    float4 s = ((const float4*)P)[i];
    #pragma unroll
    for (int z = 1; z < XP_SPLIT; z++) {
        float4 v = ((const float4*)(P + (size_t)z * BL * XDW))[i];
        s.x += v.x; s.y += v.y; s.z += v.z; s.w += v.w;
    }
    ((float4*)O)[i] = s;
}
__global__ void reduce_pw_kernel(const float* __restrict__ P, float* __restrict__ X) {
    int i = blockIdx.x * blockDim.x + threadIdx.x;      // over BL*DMODEL/4
    if (i >= BL * DMODEL / 4) return;
    float4 a = ((const float4*)P)[i];
    float4 b = ((const float4*)(P + (size_t)BL * DMODEL))[i];
    float4 x = ((float4*)X)[i];
    x.x += a.x + b.x; x.y += a.y + b.y; x.z += a.z + b.z; x.w += a.w + b.w;
    ((float4*)X)[i] = x;
}

// ---------------- fp32 -> bf16 hi/lo split (weights) ------------------------
__global__ void split_kernel(const float* __restrict__ S,
                             __nv_bfloat16* __restrict__ H,
                             __nv_bfloat16* __restrict__ L, int n4) {
    int i = blockIdx.x * blockDim.x + threadIdx.x;
    if (i >= n4) return;
    float4 v = ((const float4*)S)[i];
    __nv_bfloat16 h0 = __float2bfloat16(v.x), h1 = __float2bfloat16(v.y);
    __nv_bfloat16 h2 = __float2bfloat16(v.z), h3 = __float2bfloat16(v.w);
    __nv_bfloat16 l0 = __float2bfloat16(v.x - __bfloat162float(h0));
    __nv_bfloat16 l1 = __float2bfloat16(v.y - __bfloat162float(h1));
    __nv_bfloat16 l2 = __float2bfloat16(v.z - __bfloat162float(h2));
    __nv_bfloat16 l3 = __float2bfloat16(v.w - __bfloat162float(h3));
    __nv_bfloat162 a; a.x = h0; a.y = h1;
    __nv_bfloat162 b; b.x = h2; b.y = h3;
    ((__nv_bfloat162*)H)[i * 2] = a; ((__nv_bfloat162*)H)[i * 2 + 1] = b;
    a.x = l0; a.y = l1; b.x = l2; b.y = l3;
    ((__nv_bfloat162*)L)[i * 2] = a; ((__nv_bfloat162*)L)[i * 2 + 1] = b;
}

// ---------------- embedding gather -----------------------------------------
__global__ void embed_kernel(const int* __restrict__ ids,
                             const float* __restrict__ emb,
                             float* __restrict__ X) {
    int r = blockIdx.x;
    int id = ids[r];
    const float* src = emb + (size_t)id * DMODEL;
    float* dst = X + (size_t)r * DMODEL;
    for (int d = threadIdx.x; d < DMODEL; d += blockDim.x) dst[d] = src[d];
}

// ---------------- rmsnorm (fused bf16 hi/lo split output) -------------------
__global__ void rmsnorm_kernel(const float* __restrict__ X,
                               const float* __restrict__ w,
                               __nv_bfloat16* __restrict__ OH,
                               __nv_bfloat16* __restrict__ OL) {
    int r = blockIdx.x;
    const float* x = X + (size_t)r * DMODEL;
    float s = 0.f;
    for (int d = threadIdx.x; d < DMODEL; d += 256) { float v = x[d]; s += v * v; }
    __shared__ float sh[8];
    int lane = threadIdx.x & 31, wrp = threadIdx.x >> 5;
    #pragma unroll
    for (int o = 16; o > 0; o >>= 1) s += __shfl_xor_sync(0xffffffffu, s, o);
    if (lane == 0) sh[wrp] = s;
    __syncthreads();
    if (threadIdx.x == 0) {
        float t = 0.f;
        #pragma unroll
        for (int i = 0; i < 8; i++) t += sh[i];
        sh[0] = rsqrtf(t / (float)DMODEL + 1e-5f);
    }
    __syncthreads();
    float inv = sh[0];
    for (int d = threadIdx.x; d < DMODEL; d += 256) {
        float v = x[d] * inv * w[d];
        __nv_bfloat16 h = __float2bfloat16(v);
        OH[(size_t)r * DMODEL + d] = h;
        OL[(size_t)r * DMODEL + d] = __float2bfloat16(v - __bfloat162float(h));
    }
}

// ---------------- 3xTF32 split mma.sync GEMM (small shapes, split-K) --------
// mode 0: C = acc ; mode 2: C = softplus(acc + bias[col])
__device__ __forceinline__ uint32_t f2tf(float f) {
    uint32_t r;
    asm("cvt.rna.tf32.f32 %0, %1;" : "=r"(r) : "f"(f));
    return r;
}
#define KSTR 20

__global__ __launch_bounds__(256) void gemm_tf32s_kernel(
    const float* __restrict__ A, int lda,
    const float* __restrict__ B, int ldb,
    float* __restrict__ C, int ldc,
    int M, int N, int K, int mode, const float* __restrict__ bias, size_t czstride)
{
    __shared__ uint32_t Ash[128 * KSTR], Asl[128 * KSTR];
    __shared__ uint32_t Bsh[128 * KSTR], Bsl[128 * KSTR];

    const int tid  = threadIdx.x;
    const int warp = tid >> 5;
    const int lane = tid & 31;
    const int g = lane >> 2, t = lane & 3;
    const int wm = (warp >> 2) * 64;
    const int wn = (warp & 3) * 32;
    const int brow = blockIdx.y * 128;
    const int bcol = blockIdx.x * 128;
    const int koff = blockIdx.z * K;
    C += (size_t)blockIdx.z * czstride;
    const int gr0 = tid >> 2;
    const int gr1 = (tid + 256) >> 2;
    const int gk  = (tid & 3) * 4;

    float c[4][4][4];
    #pragma unroll
    for (int mi = 0; mi < 4; mi++)
        #pragma unroll
        for (int ni = 0; ni < 4; ni++)
            #pragma unroll
            for (int q = 0; q < 4; q++) c[mi][ni][q] = 0.f;

    const int nk = K / 16;
    float4 aR0, aR1, bR0, bR1;
    const bool bv0 = (bcol + gr0) < N;
    const bool bv1 = (bcol + gr1) < N;

    aR0 = *(const float4*)&A[(size_t)(brow + gr0) * lda + koff + gk];
    aR1 = *(const float4*)&A[(size_t)(brow + gr1) * lda + koff + gk];
    bR0 = bv0 ? *(const float4*)&B[(size_t)(bcol + gr0) * ldb + koff + gk] : make_float4(0,0,0,0);
    bR1 = bv1 ? *(const float4*)&B[(size_t)(bcol + gr1) * ldb + koff + gk] : make_float4(0,0,0,0);

    for (int kt = 0; kt < nk; kt++) {
        __syncthreads();
        #pragma unroll
        for (int q = 0; q < 4; q++) {
            float av0 = (&aR0.x)[q], av1 = (&aR1.x)[q];
            float bw0 = (&bR0.x)[q], bw1 = (&bR1.x)[q];
            uint32_t h;
            h = f2tf(av0); Ash[gr0*KSTR+gk+q] = h; Asl[gr0*KSTR+gk+q] = f2tf(av0 - __uint_as_float(h));
            h = f2tf(av1); Ash[gr1*KSTR+gk+q] = h; Asl[gr1*KSTR+gk+q] = f2tf(av1 - __uint_as_float(h));
            h = f2tf(bw0); Bsh[gr0*KSTR+gk+q] = h; Bsl[gr0*KSTR+gk+q] = f2tf(bw0 - __uint_as_float(h));
            h = f2tf(bw1); Bsh[gr1*KSTR+gk+q] = h; Bsl[gr1*KSTR+gk+q] = f2tf(bw1 - __uint_as_float(h));
        }
        __syncthreads();

        if (kt + 1 < nk) {
            int k0 = koff + (kt + 1) * 16;
            aR0 = *(const float4*)&A[(size_t)(brow + gr0) * lda + k0 + gk];
            aR1 = *(const float4*)&A[(size_t)(brow + gr1) * lda + k0 + gk];
            bR0 = bv0 ? *(const float4*)&B[(size_t)(bcol + gr0) * ldb + k0 + gk] : make_float4(0,0,0,0);
            bR1 = bv1 ? *(const float4*)&B[(size_t)(bcol + gr1) * ldb + k0 + gk] : make_float4(0,0,0,0);
        }

        #pragma unroll
        for (int ks = 0; ks < 16; ks += 8) {
            uint32_t afh[4][4], afl[4][4], bfh[4][2], bfl[4][2];
            #pragma unroll
            for (int mi = 0; mi < 4; mi++) {
                int mr = wm + mi * 16;
                afh[mi][0] = Ash[(mr+g  )*KSTR+ks+t  ]; afl[mi][0] = Asl[(mr+g  )*KSTR+ks+t  ];
                afh[mi][1] = Ash[(mr+g+8)*KSTR+ks+t  ]; afl[mi][1] = Asl[(mr+g+8)*KSTR+ks+t  ];
                afh[mi][2] = Ash[(mr+g  )*KSTR+ks+t+4]; afl[mi][2] = Asl[(mr+g  )*KSTR+ks+t+4];
                afh[mi][3] = Ash[(mr+g+8)*KSTR+ks+t+4]; afl[mi][3] = Asl[(mr+g+8)*KSTR+ks+t+4];
            }
            #pragma unroll
            for (int ni = 0; ni < 4; ni++) {
                int nr = wn + ni * 8;
                bfh[ni][0] = Bsh[(nr+g)*KSTR+ks+t  ]; bfl[ni][0] = Bsl[(nr+g)*KSTR+ks+t  ];
                bfh[ni][1] = Bsh[(nr+g)*KSTR+ks+t+4]; bfl[ni][1] = Bsl[(nr+g)*KSTR+ks+t+4];
            }
            #pragma unroll
            for (int mi = 0; mi < 4; mi++)
                #pragma unroll
                for (int ni = 0; ni < 4; ni++) {
                    #define MMA_TF32(AF, BF) \
                        asm volatile("mma.sync.aligned.m16n8k8.row.col.f32.tf32.tf32.f32 " \
                            "{%0,%1,%2,%3}, {%4,%5,%6,%7}, {%8,%9}, {%0,%1,%2,%3};\n" \
                            : "+f"(c[mi][ni][0]), "+f"(c[mi][ni][1]), \
                              "+f"(c[mi][ni][2]), "+f"(c[mi][ni][3]) \
                            : "r"(AF[mi][0]), "r"(AF[mi][1]), "r"(AF[mi][2]), "r"(AF[mi][3]), \
                              "r"(BF[ni][0]), "r"(BF[ni][1]))
                    MMA_TF32(afh, bfh);
                    MMA_TF32(afh, bfl);
                    MMA_TF32(afl, bfh);
                    #undef MMA_TF32
                }
        }
    }

    #pragma unroll
    for (int mi = 0; mi < 4; mi++) {
        int r0 = brow + wm + mi * 16 + g;
        #pragma unroll
        for (int ni = 0; ni < 4; ni++) {
            int col = bcol + wn + ni * 8 + 2 * t;
            #pragma unroll
            for (int q = 0; q < 4; q++) {
                int rr = r0 + (q >> 1) * 8;
                int cc = col + (q & 1);
                if (cc < N) {
                    size_t idx = (size_t)rr * ldc + cc;
                    float v = c[mi][ni][q];
                    if (mode == 2) {
                        v += bias[cc];
                        v = fmaxf(v, 0.f) + log1pf(expf(-fabsf(v)));
                    }
                    C[idx] = v;
                }
            }
        }
    }
}

// ---------------- depthwise causal conv (k=4) + silu ------------------------
__global__ void conv_silu_kernel(const float* __restrict__ XZ,
                                 const float* __restrict__ cw,
                                 const float* __restrict__ cb,
                                 float* __restrict__ U) {
    int d = blockIdx.x * blockDim.x + threadIdx.x;
    int r = blockIdx.y;
    if (d >= DINNER) return;
    int l = r & (LL - 1);
    float w0 = cw[d*4+0], w1 = cw[d*4+1], w2 = cw[d*4+2], w3 = cw[d*4+3];
    const float* Xp = XZ + (size_t)r * (2 * DINNER) + d;
    float acc = cb[d] + w3 * Xp[0];
    if (l >= 1) acc += w2 * Xp[-(2 * DINNER)];
    if (l >= 2) acc += w1 * Xp[-2 * (2 * DINNER)];
    if (l >= 3) acc += w0 * Xp[-3 * (2 * DINNER)];
    U[(size_t)r * DINNER + d] = acc / (1.f + expf(-acc));
}

// ---------------- selective scan (exp-of-suffix-cumsum formulation) ---------
__global__ void scan_kernel(const float* __restrict__ DT, const float* __restrict__ U,
                            const float* __restrict__ XD, const float* __restrict__ Alog,
                            const float* __restrict__ Dp, const float* __restrict__ XZ,
                            __nv_bfloat16* __restrict__ YH, __nv_bfloat16* __restrict__ YL,
                            float* __restrict__ SC)
{
    int b  = blockIdx.y;
    int n  = threadIdx.x & 15;
    int dl = threadIdx.x >> 4;
    int d  = blockIdx.x * 16 + dl;
    float A = -expf(Alog[d * DSTATE + n]);
    size_t cbase = ((size_t)b * DINNER * DSTATE + (size_t)d * DSTATE + n) * NCHK;

    float S = 0.f;
    for (int l = LL - 1; l >= 0; --l) {
        int r = b * LL + l;
        if ((l & (CHK - 1)) == 0) SC[cbase + (l >> 7)] = S;
        S += DT[(size_t)r * DINNER + d] * A;
    }

    float num = 0.f;
    float Dv = Dp[d];
    S = 0.f;
    for (int l = 0; l < LL; ++l) {
        int r = b * LL + l;
        float dt = DT[(size_t)r * DINNER + d];
        if ((l & (CHK - 1)) == 0) S = SC[cbase + (l >> 7)];
        else S -= dt * A;
        float es = expf(S);
        float u  = U[(size_t)r * DINNER + d];
        float Bm = XD[(size_t)r * XDW + DTRANK + n];
        float Cm = XD[(size_t)r * XDW + DTRANK + DSTATE + n];
        num += dt * u * Bm * es;
        float part = (num / (es + 1e-12f)) * Cm;
        part += __shfl_xor_sync(0xffffffffu, part, 8);
        part += __shfl_xor_sync(0xffffffffu, part, 4);
        part += __shfl_xor_sync(0xffffffffu, part, 2);
        part += __shfl_xor_sync(0xffffffffu, part, 1);
        if (n == 0) {
            float y   = part + u * Dv;
            float res = XZ[(size_t)r * (2 * DINNER) + DINNER + d];
            float yv  = y * (res / (1.f + expf(-res)));
            __nv_bfloat16 h = __float2bfloat16(yv);
            YH[(size_t)r * DINNER + d] = h;
            YL[(size_t)r * DINNER + d] = __float2bfloat16(yv - __bfloat162float(h));
        }
    }
}

// ---------------- driver ----------------------------------------------------
extern "C" void kernel_launch(void* const* d_in, const int* in_sizes, int n_in,
                              void* d_out, int out_size) {
    const int*   ids       = (const int*)  d_in[0];
    const float* emb       = (const float*)d_in[1];
    const float* W_in      = (const float*)d_in[2];
    const float* conv_w    = (const float*)d_in[3];
    const float* conv_b    = (const float*)d_in[4];
    const float* x_proj_w  = (const float*)d_in[5];
    const float* dt_proj_w = (const float*)d_in[6];
    const float* dt_proj_b = (const float*)d_in[7];
    const float* A_log     = (const float*)d_in[8];
    const float* D_param   = (const float*)d_in[9];
    const float* W_out     = (const float*)d_in[10];
    const float* norm_w    = (const float*)d_in[11];
    const float* norm_f_w  = (const float*)d_in[12];
    float* out = (float*)d_out;

    float *pX, *pXZ, *pU, *pXDBL, *pDT, *pSC, *pXP, *pPW;
    __nv_bfloat16 *pXNh, *pXNl, *pYh, *pYl, *pEh, *pEl, *pWih, *pWil, *pWoh, *pWol;
    cudaGetSymbolAddress((void**)&pX,    g_X);
    cudaGetSymbolAddress((void**)&pXZ,   g_XZ);
    cudaGetSymbolAddress((void**)&pU,    g_U);
    cudaGetSymbolAddress((void**)&pXDBL, g_XDBL);
    cudaGetSymbolAddress((void**)&pDT,   g_DT);
    cudaGetSymbolAddress((void**)&pSC,   g_SC);
    cudaGetSymbolAddress((void**)&pXP,   g_XP);
    cudaGetSymbolAddress((void**)&pPW,   g_PW);
    cudaGetSymbolAddress((void**)&pXNh,  g_XNh);
    cudaGetSymbolAddress((void**)&pXNl,  g_XNl);
    cudaGetSymbolAddress((void**)&pYh,   g_Yh);
    cudaGetSymbolAddress((void**)&pYl,   g_Yl);
    cudaGetSymbolAddress((void**)&pEh,   g_Eh);
    cudaGetSymbolAddress((void**)&pEl,   g_El);
    cudaGetSymbolAddress((void**)&pWih,  g_Wih);
    cudaGetSymbolAddress((void**)&pWil,  g_Wil);
    cudaGetSymbolAddress((void**)&pWoh,  g_Woh);
    cudaGetSymbolAddress((void**)&pWol,  g_Wol);

    static int smem_set = 0;
    if (!smem_set) {
        cudaFuncSetAttribute(gemm_bf16s_kernel,
                             cudaFuncAttributeMaxDynamicSharedMemorySize, GSMEM);
        smem_set = 1;
    }

    embed_kernel<<<BL, 256>>>(ids, emb, pX);                                     // 0

    for (int i = 0; i < NLAYER; i++) {
        split_kernel<<<(2 * DINNER * DMODEL / 4 + 255) / 256, 256>>>(            // 1
            W_in + (size_t)i * 2 * DINNER * DMODEL, pWih, pWil, 2 * DINNER * DMODEL / 4);

        rmsnorm_kernel<<<BL, 256>>>(pX, norm_w + (size_t)i * DMODEL, pXNh, pXNl);// 2

        // xz = xn @ W_in^T : (2048,3072) K=768
        gemm_bf16s_kernel<<<dim3(BL / 128, 2 * DINNER / 128, 1), 256, GSMEM>>>(  // 3
            pXNh, pXNl, pWih, pWil, pXZ, 2 * DINNER, DMODEL, DMODEL, 0, 0);

        conv_silu_kernel<<<dim3(DINNER / 256, BL), 256>>>(
            pXZ, conv_w + (size_t)i * DINNER * 4, conv_b + (size_t)i * DINNER, pU);

        // x_dbl = u @ x_proj_w^T : (2048,80) K=1536, split-K=12 -> partials
        gemm_tf32s_kernel<<<dim3(1, BL / 128, XP_SPLIT), 256>>>(
            pU, DINNER, x_proj_w + (size_t)i * XDW * DINNER, DINNER,
            pXP, XDW, BL, XDW, DINNER / XP_SPLIT, 0, nullptr, (size_t)BL * XDW);
        reduce_xp_kernel<<<(BL * XDW / 4 + 255) / 256, 256>>>(pXP, pXDBL);

        // dt = softplus(x_dbl[:, :48] @ dt_proj_w^T + b)
        gemm_tf32s_kernel<<<dim3(DINNER / 128, BL / 128, 1), 256>>>(
            pXDBL, XDW, dt_proj_w + (size_t)i * DINNER * DTRANK, DTRANK,
            pDT, DINNER, BL, DINNER, DTRANK, 2, dt_proj_b + (size_t)i * DINNER, 0);

        scan_kernel<<<dim3(DINNER / 16, BB), 256>>>(
            pDT, pU, pXDBL, A_log + (size_t)i * DINNER * DSTATE,
            D_param + (size_t)i * DINNER, pXZ, pYh, pYl, pSC);

        split_kernel<<<(DMODEL * DINNER / 4 + 255) / 256, 256>>>(
            W_out + (size_t)i * DMODEL * DINNER, pWoh, pWol, DMODEL * DINNER / 4);

        // y @ W_out^T : (2048,768) K=1536, split-K=2 -> partials, then add to X
        gemm_bf16s_kernel<<<dim3(BL / 128, DMODEL / 128, WO_SPLIT), 256, GSMEM>>>(
            pYh, pYl, pWoh, pWol, pPW, DMODEL, DINNER, DINNER / WO_SPLIT, 0,
            (size_t)BL * DMODEL);
        reduce_pw_kernel<<<(BL * DMODEL / 4 + 255) / 256, 256>>>(pPW, pX);
    }

    rmsnorm_kernel<<<BL, 256>>>(pX, norm_f_w, pXNh, pXNl);

    split_kernel<<<(VOCAB * DMODEL / 4 + 255) / 256, 256>>>(emb, pEh, pEl, VOCAB * DMODEL / 4);

    // logits = xn @ emb^T : (2048,32000) K=768
    gemm_bf16s_kernel<<<dim3(BL / 128, VOCAB / 128, 1), 256, GSMEM>>>(
        pXNh, pXNl, pEh, pEl, out, VOCAB, DMODEL, DMODEL, 0, 0);
}